// round 8
// baseline (speedup 1.0000x reference)
#include <cuda_runtime.h>
#include <cuda_bf16.h>
#include <stdint.h>

// Problem constants (B=4, S=4096, HID=1024, H=16, D=64)
#define GM 16384
#define GN 1024
#define GK 1024
#define NPOS 16384
#define ATT_ELEMS (NPOS * 256)
#define MAIN_OUT_ELEMS (GM * GN)
#define ASLOT ((size_t)GM * GK)
#define WSLOT ((size_t)GN * GK)

// Device-global scratch (no allocations allowed)
__device__ __align__(16) float g_Q[GM * GN];
__device__ __align__(16) float g_K[GM * GN];
__device__ __align__(16) float g_V[GM * GN];
// A-operand splits: slot 0 = query (later reused for X), 1 = key, 2 = value
__device__ __align__(16) __nv_bfloat16 g_Ah[3 * ASLOT];
__device__ __align__(16) __nv_bfloat16 g_Al[3 * ASLOT];
// W^T splits: slot 0..3 = Wq, Wk, Wv, Wo   ([n][k] layout)
__device__ __align__(16) __nv_bfloat16 g_Wth[4 * WSLOT];
__device__ __align__(16) __nv_bfloat16 g_Wtl[4 * WSLOT];

// ---------------------------------------------------------------------------
// helpers
// ---------------------------------------------------------------------------
__device__ __forceinline__ void mma16816(float* c, const uint32_t* a, uint32_t b0, uint32_t b1) {
    asm volatile(
        "mma.sync.aligned.m16n8k16.row.col.f32.bf16.bf16.f32 "
        "{%0,%1,%2,%3}, {%4,%5,%6,%7}, {%8,%9}, {%0,%1,%2,%3};"
        : "+f"(c[0]), "+f"(c[1]), "+f"(c[2]), "+f"(c[3])
        : "r"(a[0]), "r"(a[1]), "r"(a[2]), "r"(a[3]), "r"(b0), "r"(b1));
}

__device__ __forceinline__ void ldsm4(uint32_t* r, uint32_t addr) {
    asm volatile("ldmatrix.sync.aligned.m8n8.x4.shared.b16 {%0,%1,%2,%3}, [%4];"
                 : "=r"(r[0]), "=r"(r[1]), "=r"(r[2]), "=r"(r[3]) : "r"(addr));
}

__device__ __forceinline__ void cp16(uint32_t dst, const void* src) {
    asm volatile("cp.async.cg.shared.global [%0], [%1], 16;" :: "r"(dst), "l"(src));
}

// ---------------------------------------------------------------------------
// Split kernels (merged: one launch covers all inputs)
// ---------------------------------------------------------------------------
__global__ __launch_bounds__(256) void split_a3_kernel(
    const float* __restrict__ q, const float* __restrict__ k,
    const float* __restrict__ v)
{
    const int z = blockIdx.z;
    const float* A = (z == 0) ? q : (z == 1) ? k : v;
    size_t idx = (size_t)blockIdx.x * 256 + threadIdx.x;   // float4 index
    float4 vv = reinterpret_cast<const float4*>(A)[idx];
    __nv_bfloat16 h0 = __float2bfloat16_rn(vv.x), h1 = __float2bfloat16_rn(vv.y);
    __nv_bfloat16 h2 = __float2bfloat16_rn(vv.z), h3 = __float2bfloat16_rn(vv.w);
    __nv_bfloat16 l0 = __float2bfloat16_rn(vv.x - __bfloat162float(h0));
    __nv_bfloat16 l1 = __float2bfloat16_rn(vv.y - __bfloat162float(h1));
    __nv_bfloat16 l2 = __float2bfloat16_rn(vv.z - __bfloat162float(h2));
    __nv_bfloat16 l3 = __float2bfloat16_rn(vv.w - __bfloat162float(h3));
    __nv_bfloat162* Hp = reinterpret_cast<__nv_bfloat162*>(g_Ah + (size_t)z * ASLOT);
    __nv_bfloat162* Lp = reinterpret_cast<__nv_bfloat162*>(g_Al + (size_t)z * ASLOT);
    Hp[idx * 2]     = __halves2bfloat162(h0, h1);
    Hp[idx * 2 + 1] = __halves2bfloat162(h2, h3);
    Lp[idx * 2]     = __halves2bfloat162(l0, l1);
    Lp[idx * 2 + 1] = __halves2bfloat162(l2, l3);
}

__global__ __launch_bounds__(256) void split_wt4_kernel(
    const float* __restrict__ w0, const float* __restrict__ w1,
    const float* __restrict__ w2, const float* __restrict__ w3)
{
    const int z = blockIdx.z;
    const float* W = (z == 0) ? w0 : (z == 1) ? w1 : (z == 2) ? w2 : w3;
    __nv_bfloat16* Wh = g_Wth + (size_t)z * WSLOT;
    __nv_bfloat16* Wl = g_Wtl + (size_t)z * WSLOT;

    __shared__ float t[32][33];
    int n0 = blockIdx.x * 32, k0 = blockIdx.y * 32;
    int tx = threadIdx.x & 31, ty = threadIdx.x >> 5;
    #pragma unroll
    for (int j = 0; j < 4; j++)
        t[ty + 8 * j][tx] = W[(size_t)(k0 + ty + 8 * j) * GN + n0 + tx];
    __syncthreads();
    #pragma unroll
    for (int j = 0; j < 4; j++) {
        int r = ty + 8 * j;
        float v = t[tx][r];
        __nv_bfloat16 h = __float2bfloat16_rn(v);
        __nv_bfloat16 l = __float2bfloat16_rn(v - __bfloat162float(h));
        Wh[(size_t)(n0 + r) * GK + k0 + tx] = h;
        Wl[(size_t)(n0 + r) * GK + k0 + tx] = l;
    }
}

// ---------------------------------------------------------------------------
// GEMM: C = A @ W + bias, pre-split bf16 hi/lo operands.
// CTA 128x128, BK=32. 512 threads = 16 warps (4x4 grid), warp tile 32x32.
// 2-stage cp.async pipeline, ldmatrix fragments, 3-term compensated MMA.
// ~96 regs/thread -> no spills, 16 warps/SM (4/SMSP) to feed the HMMA pipe.
// ---------------------------------------------------------------------------
#define TILE_B   10240              // 128 rows * 80 B
#define STAGE_B  (4 * TILE_B)       // Ah, Al, Bh, Bl
#define GSMEM    (2 * STAGE_B)      // 81920

__device__ __forceinline__ float* out_ptr(int tag) {
    switch (tag) { case 1: return g_Q; case 2: return g_K; default: return g_V; }
}

__global__ __launch_bounds__(512, 1) void gemm_tc_kernel(
    int a_slot, int w_slot, float* Cout, int c_tag, const float* __restrict__ bias)
{
    const __nv_bfloat16* Ah = g_Ah + (size_t)a_slot * ASLOT;
    const __nv_bfloat16* Al = g_Al + (size_t)a_slot * ASLOT;
    const __nv_bfloat16* Bh = g_Wth + (size_t)w_slot * WSLOT;
    const __nv_bfloat16* Bl = g_Wtl + (size_t)w_slot * WSLOT;
    float* C = Cout ? Cout : out_ptr(c_tag);

    extern __shared__ __align__(16) char sm[];
    const uint32_t smbase = (uint32_t)__cvta_generic_to_shared(sm);

    const int tid  = threadIdx.x;
    const int warp = tid >> 5;          // 0..15
    const int lane = tid & 31;
    const int gid  = lane >> 2;
    const int tig  = lane & 3;
    const int wm = (warp >> 2) * 32;    // 0,32,64,96
    const int wn = (warp & 3) * 32;     // 0,32,64,96
    const int bm = blockIdx.y * 128;
    const int bn = blockIdx.x * 128;

    // copy coords: 512 threads x 1 (row, chunk) covers one 128x80B tile
    const int crow = tid >> 2, cch = tid & 3;

    float acc[2][4][4];
    #pragma unroll
    for (int a = 0; a < 2; a++)
        #pragma unroll
        for (int b = 0; b < 4; b++)
            #pragma unroll
            for (int c = 0; c < 4; c++) acc[a][b][c] = 0.f;

    auto stage_copy = [&](int s, int kt) {
        uint32_t st = smbase + s * STAGE_B;
        const int kof = kt * 32;
        const __nv_bfloat16* ah = Ah + (size_t)(bm + crow) * GK + kof + cch * 8;
        const __nv_bfloat16* al = Al + (size_t)(bm + crow) * GK + kof + cch * 8;
        const __nv_bfloat16* bh = Bh + (size_t)(bn + crow) * GK + kof + cch * 8;
        const __nv_bfloat16* bl = Bl + (size_t)(bn + crow) * GK + kof + cch * 8;
        uint32_t d = st + crow * 80 + cch * 16;
        cp16(d, ah); cp16(d + TILE_B, al);
        cp16(d + 2 * TILE_B, bh); cp16(d + 3 * TILE_B, bl);
        asm volatile("cp.async.commit_group;" ::: "memory");
    };

    stage_copy(0, 0);

    for (int kt = 0; kt < 32; kt++) {
        if (kt + 1 < 32) {
            stage_copy((kt + 1) & 1, kt + 1);
            asm volatile("cp.async.wait_group 1;" ::: "memory");
        } else {
            asm volatile("cp.async.wait_group 0;" ::: "memory");
        }
        __syncthreads();

        uint32_t st = smbase + (kt & 1) * STAGE_B;
        #pragma unroll
        for (int ks = 0; ks < 2; ks++) {
            const int kof = ks * 16;
            uint32_t ah[2][4], al[2][4];
            #pragma unroll
            for (int mi = 0; mi < 2; mi++) {
                uint32_t addr = st + (wm + mi * 16 + (lane & 15)) * 80
                              + (kof + (lane >> 4) * 8) * 2;
                ldsm4(ah[mi], addr);
                ldsm4(al[mi], addr + TILE_B);
            }
            #pragma unroll
            for (int nip = 0; nip < 2; nip++) {
                uint32_t baddr = st + 2 * TILE_B
                               + (wn + nip * 16 + (lane & 7) + ((lane >> 4) << 3)) * 80
                               + (kof + ((lane >> 3) & 1) * 8) * 2;
                uint32_t bh[4], bl[4];
                ldsm4(bh, baddr);
                ldsm4(bl, baddr + TILE_B);
                #pragma unroll
                for (int mi = 0; mi < 2; mi++) {
                    mma16816(acc[mi][2 * nip],     ah[mi], bh[0], bh[1]);
                    mma16816(acc[mi][2 * nip],     ah[mi], bl[0], bl[1]);
                    mma16816(acc[mi][2 * nip],     al[mi], bh[0], bh[1]);
                    mma16816(acc[mi][2 * nip + 1], ah[mi], bh[2], bh[3]);
                    mma16816(acc[mi][2 * nip + 1], ah[mi], bl[2], bl[3]);
                    mma16816(acc[mi][2 * nip + 1], al[mi], bh[2], bh[3]);
                }
            }
        }
        __syncthreads();
    }

    // epilogue: bias + store
    #pragma unroll
    for (int mi = 0; mi < 2; mi++) {
        int row = bm + wm + mi * 16 + gid;
        #pragma unroll
        for (int ni = 0; ni < 4; ni++) {
            int col = bn + wn + ni * 8 + tig * 2;
            float b0 = bias[col], b1 = bias[col + 1];
            float2 r01 = make_float2(acc[mi][ni][0] + b0, acc[mi][ni][1] + b1);
            float2 r23 = make_float2(acc[mi][ni][2] + b0, acc[mi][ni][3] + b1);
            *reinterpret_cast<float2*>(&C[(size_t)row * GN + col])       = r01;
            *reinterpret_cast<float2*>(&C[(size_t)(row + 8) * GN + col]) = r23;
        }
    }
}

// ---------------------------------------------------------------------------
// Per-position attention. Reads g_Q/g_K/g_V; writes X as bf16 hi/lo directly
// into A-split slot 0 ((B,H,S,D) layout = A operand of output projection).
// ---------------------------------------------------------------------------
__global__ __launch_bounds__(256) void attn_kernel(
    const float* __restrict__ SW, float* AT)
{
    const int p = blockIdx.x;
    const int b = p >> 12;
    const int s = p & 4095;
    const int tid = threadIdx.x;

    __shared__ __align__(16) float qs[16][65];
    __shared__ __align__(16) float ks_[16][65];
    __shared__ __align__(16) float vs[16][64];
    __shared__ float qn2[16], kn2[16];
    __shared__ float att[16][16];

    const size_t base = (size_t)p * 1024;
    {
        int e = tid * 4;
        int r = e >> 6, d = e & 63;
        float4 qv = *reinterpret_cast<const float4*>(g_Q + base + e);
        float4 kv = *reinterpret_cast<const float4*>(g_K + base + e);
        float4 vv = *reinterpret_cast<const float4*>(g_V + base + e);
        qs[r][d] = qv.x; qs[r][d + 1] = qv.y; qs[r][d + 2] = qv.z; qs[r][d + 3] = qv.w;
        ks_[r][d] = kv.x; ks_[r][d + 1] = kv.y; ks_[r][d + 2] = kv.z; ks_[r][d + 3] = kv.w;
        *reinterpret_cast<float4*>(&vs[r][d]) = vv;
    }
    float w0, w1, w2;
    {
        float s0 = SW[0], s1 = SW[1], s2 = SW[2];
        float mx = fmaxf(s0, fmaxf(s1, s2));
        float e0 = expf(s0 - mx), e1 = expf(s1 - mx), e2 = expf(s2 - mx);
        float inv = 1.f / (e0 + e1 + e2);
        w0 = e0 * inv; w1 = e1 * inv; w2 = e2 * inv;
    }
    __syncthreads();

    if (tid < 32) {
        int r = tid & 15;
        const float* src = (tid < 16) ? qs[r] : ks_[r];
        float ssum = 0.f;
        #pragma unroll 8
        for (int d = 0; d < 64; d++) ssum += src[d] * src[d];
        if (tid < 16) qn2[r] = ssum; else kn2[r] = ssum;
    }
    __syncthreads();

    {
        int i = tid >> 4, j = tid & 15;
        float qk = 0.f;
        #pragma unroll 8
        for (int d = 0; d < 64; d++) qk += qs[i][d] * ks_[j][d];
        float sq = qn2[i], sk = kn2[j];
        float dots  = qk * 0.125f;
        float denom = fmaxf(sqrtf(sq) * sqrtf(sk), 1e-8f);
        float cosv  = qk / denom;
        float d2    = fmaxf(sq + sk - 2.f * qk, 0.f);
        float dist  = -sqrtf(d2);
        float sc = w0 * dots + w1 * cosv + w2 * dist;

        float mx = sc;
        #pragma unroll
        for (int o = 8; o; o >>= 1) mx = fmaxf(mx, __shfl_xor_sync(0xffffffffu, mx, o, 16));
        float e = expf(sc - mx);
        float sm = e;
        #pragma unroll
        for (int o = 8; o; o >>= 1) sm += __shfl_xor_sync(0xffffffffu, sm, o, 16);
        float a = e / sm;
        att[i][j] = a;
        if (AT) AT[(size_t)p * 256 + tid] = a;
    }
    __syncthreads();

    {
        int i = tid >> 4, d0 = (tid & 15) * 4;
        float4 o = make_float4(0.f, 0.f, 0.f, 0.f);
        #pragma unroll
        for (int j = 0; j < 16; j++) {
            float a = att[i][j];
            float4 v4 = *reinterpret_cast<const float4*>(&vs[j][d0]);
            o.x += a * v4.x; o.y += a * v4.y; o.z += a * v4.z; o.w += a * v4.w;
        }
        size_t xidx = (size_t)b * 4194304 + (size_t)i * 262144 + (size_t)s * 64 + d0;
        __nv_bfloat16 h0 = __float2bfloat16_rn(o.x), h1 = __float2bfloat16_rn(o.y);
        __nv_bfloat16 h2 = __float2bfloat16_rn(o.z), h3 = __float2bfloat16_rn(o.w);
        __nv_bfloat16 l0 = __float2bfloat16_rn(o.x - __bfloat162float(h0));
        __nv_bfloat16 l1 = __float2bfloat16_rn(o.y - __bfloat162float(h1));
        __nv_bfloat16 l2 = __float2bfloat16_rn(o.z - __bfloat162float(h2));
        __nv_bfloat16 l3 = __float2bfloat16_rn(o.w - __bfloat162float(h3));
        __nv_bfloat162 hh0 = __halves2bfloat162(h0, h1), hh1 = __halves2bfloat162(h2, h3);
        __nv_bfloat162 ll0 = __halves2bfloat162(l0, l1), ll1 = __halves2bfloat162(l2, l3);
        uint2 hp = make_uint2(*reinterpret_cast<uint32_t*>(&hh0), *reinterpret_cast<uint32_t*>(&hh1));
        uint2 lp = make_uint2(*reinterpret_cast<uint32_t*>(&ll0), *reinterpret_cast<uint32_t*>(&ll1));
        *reinterpret_cast<uint2*>(&g_Ah[xidx]) = hp;   // slot 0
        *reinterpret_cast<uint2*>(&g_Al[xidx]) = lp;   // slot 0
    }
}

// ---------------------------------------------------------------------------
// kernel_launch — 4th launch (profiled) is a GEMM.
// ---------------------------------------------------------------------------
extern "C" void kernel_launch(void* const* d_in, const int* in_sizes, int n_in,
                              void* d_out, int out_size) {
    (void)in_sizes; (void)n_in;
    const float* query = (const float*)d_in[0];
    const float* key   = (const float*)d_in[1];
    const float* value = (const float*)d_in[2];
    const float* Wq = (const float*)d_in[3];
    const float* bq = (const float*)d_in[4];
    const float* Wk = (const float*)d_in[5];
    const float* bk = (const float*)d_in[6];
    const float* Wv = (const float*)d_in[7];
    const float* bv = (const float*)d_in[8];
    const float* Wo = (const float*)d_in[9];
    const float* bo = (const float*)d_in[10];
    const float* sw = (const float*)d_in[11];
    float* out = (float*)d_out;

    static bool attr_set = false;
    if (!attr_set) {
        cudaFuncSetAttribute(gemm_tc_kernel,
                             cudaFuncAttributeMaxDynamicSharedMemorySize, GSMEM);
        attr_set = true;
    }

    dim3 ggrid(GN / 128, GM / 128);            // (8, 128)
    dim3 sagrid((GM * GK) / (256 * 4), 1, 3);  // (16384, 1, 3)
    dim3 swgrid(GN / 32, GK / 32, 4);          // (32, 32, 4)

    // 1: all A splits  2: all W^T splits
    split_a3_kernel<<<sagrid, 256>>>(query, key, value);
    split_wt4_kernel<<<swgrid, 256>>>(Wq, Wk, Wv, Wo);

    // 3,4,5: Q, K (profiled), V projections
    gemm_tc_kernel<<<ggrid, 512, GSMEM>>>(0, 0, nullptr, 1, bq);
    gemm_tc_kernel<<<ggrid, 512, GSMEM>>>(1, 1, nullptr, 2, bk);
    gemm_tc_kernel<<<ggrid, 512, GSMEM>>>(2, 2, nullptr, 3, bv);

    // 6: attention (writes X splits into slot 0)
    float* attn_dst = (out_size >= MAIN_OUT_ELEMS + ATT_ELEMS) ? (out + MAIN_OUT_ELEMS)
                                                               : nullptr;
    attn_kernel<<<NPOS, 256>>>(sw, attn_dst);

    // 7: output projection
    gemm_tc_kernel<<<ggrid, 512, GSMEM>>>(0, 3, out, 0, bo);
}

// round 9
// speedup vs baseline: 1.2870x; 1.2870x over previous
#include <cuda_runtime.h>
#include <cuda_fp16.h>
#include <stdint.h>

// Problem constants (B=4, S=4096, HID=1024, H=16, D=64)
#define GM 16384
#define GN 1024
#define GK 1024
#define NPOS 16384
#define ATT_ELEMS (NPOS * 256)
#define MAIN_OUT_ELEMS (GM * GN)
#define ASLOT ((size_t)GM * GK)
#define WSLOT ((size_t)GN * GK)

// Device-global scratch (no allocations allowed)
__device__ __align__(16) float g_Q[GM * GN];
__device__ __align__(16) float g_K[GM * GN];
__device__ __align__(16) float g_V[GM * GN];
// A-operand fp16 hi: slot 0 = query (later reused for X), 1 = key, 2 = value
__device__ __align__(16) __half g_Ah[3 * ASLOT];
// W^T fp16 hi/lo: slot 0..3 = Wq, Wk, Wv, Wo   ([n][k] layout)
__device__ __align__(16) __half g_Wth[4 * WSLOT];
__device__ __align__(16) __half g_Wtl[4 * WSLOT];

// ---------------------------------------------------------------------------
// helpers
// ---------------------------------------------------------------------------
__device__ __forceinline__ void mma16816(float* c, const uint32_t* a, uint32_t b0, uint32_t b1) {
    asm volatile(
        "mma.sync.aligned.m16n8k16.row.col.f32.f16.f16.f32 "
        "{%0,%1,%2,%3}, {%4,%5,%6,%7}, {%8,%9}, {%0,%1,%2,%3};"
        : "+f"(c[0]), "+f"(c[1]), "+f"(c[2]), "+f"(c[3])
        : "r"(a[0]), "r"(a[1]), "r"(a[2]), "r"(a[3]), "r"(b0), "r"(b1));
}

__device__ __forceinline__ void ldsm4(uint32_t* r, uint32_t addr) {
    asm volatile("ldmatrix.sync.aligned.m8n8.x4.shared.b16 {%0,%1,%2,%3}, [%4];"
                 : "=r"(r[0]), "=r"(r[1]), "=r"(r[2]), "=r"(r[3]) : "r"(addr));
}

__device__ __forceinline__ void cp16(uint32_t dst, const void* src) {
    asm volatile("cp.async.cg.shared.global [%0], [%1], 16;" :: "r"(dst), "l"(src));
}

// ---------------------------------------------------------------------------
// Split kernels (merged: one launch covers all inputs)
// ---------------------------------------------------------------------------
// fp32 [M,K] -> fp16 hi only, same layout. blockIdx.z selects input & slot.
__global__ __launch_bounds__(256) void split_a3_kernel(
    const float* __restrict__ q, const float* __restrict__ k,
    const float* __restrict__ v)
{
    const int z = blockIdx.z;
    const float* A = (z == 0) ? q : (z == 1) ? k : v;
    size_t idx = (size_t)blockIdx.x * 256 + threadIdx.x;   // float4 index
    float4 vv = reinterpret_cast<const float4*>(A)[idx];
    __half2 h01 = __floats2half2_rn(vv.x, vv.y);
    __half2 h23 = __floats2half2_rn(vv.z, vv.w);
    __half2* Hp = reinterpret_cast<__half2*>(g_Ah + (size_t)z * ASLOT);
    Hp[idx * 2]     = h01;
    Hp[idx * 2 + 1] = h23;
}

// W fp32 [K,N] -> fp16 [N,K] hi + lo (transpose + split). blockIdx.z selects W.
__global__ __launch_bounds__(256) void split_wt4_kernel(
    const float* __restrict__ w0, const float* __restrict__ w1,
    const float* __restrict__ w2, const float* __restrict__ w3)
{
    const int z = blockIdx.z;
    const float* W = (z == 0) ? w0 : (z == 1) ? w1 : (z == 2) ? w2 : w3;
    __half* Wh = g_Wth + (size_t)z * WSLOT;
    __half* Wl = g_Wtl + (size_t)z * WSLOT;

    __shared__ float t[32][33];
    int n0 = blockIdx.x * 32, k0 = blockIdx.y * 32;
    int tx = threadIdx.x & 31, ty = threadIdx.x >> 5;
    #pragma unroll
    for (int j = 0; j < 4; j++)
        t[ty + 8 * j][tx] = W[(size_t)(k0 + ty + 8 * j) * GN + n0 + tx];
    __syncthreads();
    #pragma unroll
    for (int j = 0; j < 4; j++) {
        int r = ty + 8 * j;
        float v = t[tx][r];
        __half h = __float2half_rn(v);
        __half l = __float2half_rn(v - __half2float(h));
        Wh[(size_t)(n0 + r) * GK + k0 + tx] = h;
        Wl[(size_t)(n0 + r) * GK + k0 + tx] = l;
    }
}

// ---------------------------------------------------------------------------
// GEMM: C = A @ W + bias. A = fp16 hi; W = fp16 hi+lo.
// 2-term compensated: acc += ah*bh + ah*bl  (== ah * W exactly in fp32)
// CTA 128x128, BK=32, 512 threads = 16 warps (4x4), warp tile 32x32.
// 2-stage cp.async pipeline, ldmatrix fragments.
// ---------------------------------------------------------------------------
#define TILE_B   10240              // 128 rows * 80 B
#define STAGE_B  (3 * TILE_B)       // Ah, Bh, Bl
#define GSMEM    (2 * STAGE_B)      // 61440

__device__ __forceinline__ float* out_ptr(int tag) {
    switch (tag) { case 1: return g_Q; case 2: return g_K; default: return g_V; }
}

__global__ __launch_bounds__(512, 1) void gemm_tc_kernel(
    int a_slot, int w_slot, float* Cout, int c_tag, const float* __restrict__ bias)
{
    const __half* Ah = g_Ah + (size_t)a_slot * ASLOT;
    const __half* Bh = g_Wth + (size_t)w_slot * WSLOT;
    const __half* Bl = g_Wtl + (size_t)w_slot * WSLOT;
    float* C = Cout ? Cout : out_ptr(c_tag);

    extern __shared__ __align__(16) char sm[];
    const uint32_t smbase = (uint32_t)__cvta_generic_to_shared(sm);

    const int tid  = threadIdx.x;
    const int warp = tid >> 5;          // 0..15
    const int lane = tid & 31;
    const int gid  = lane >> 2;
    const int tig  = lane & 3;
    const int wm = (warp >> 2) * 32;    // 0,32,64,96
    const int wn = (warp & 3) * 32;     // 0,32,64,96
    const int bm = blockIdx.y * 128;
    const int bn = blockIdx.x * 128;

    // copy coords: 512 threads x 1 (row, chunk) covers one 128x80B tile
    const int crow = tid >> 2, cch = tid & 3;

    float acc[2][4][4];
    #pragma unroll
    for (int a = 0; a < 2; a++)
        #pragma unroll
        for (int b = 0; b < 4; b++)
            #pragma unroll
            for (int c = 0; c < 4; c++) acc[a][b][c] = 0.f;

    auto stage_copy = [&](int s, int kt) {
        uint32_t st = smbase + s * STAGE_B;
        const int kof = kt * 32;
        const __half* ah = Ah + (size_t)(bm + crow) * GK + kof + cch * 8;
        const __half* bh = Bh + (size_t)(bn + crow) * GK + kof + cch * 8;
        const __half* bl = Bl + (size_t)(bn + crow) * GK + kof + cch * 8;
        uint32_t d = st + crow * 80 + cch * 16;
        cp16(d, ah);
        cp16(d + TILE_B, bh);
        cp16(d + 2 * TILE_B, bl);
        asm volatile("cp.async.commit_group;" ::: "memory");
    };

    stage_copy(0, 0);

    for (int kt = 0; kt < 32; kt++) {
        if (kt + 1 < 32) {
            stage_copy((kt + 1) & 1, kt + 1);
            asm volatile("cp.async.wait_group 1;" ::: "memory");
        } else {
            asm volatile("cp.async.wait_group 0;" ::: "memory");
        }
        __syncthreads();

        uint32_t st = smbase + (kt & 1) * STAGE_B;
        #pragma unroll
        for (int ks = 0; ks < 2; ks++) {
            const int kof = ks * 16;
            uint32_t ah[2][4];
            #pragma unroll
            for (int mi = 0; mi < 2; mi++) {
                uint32_t addr = st + (wm + mi * 16 + (lane & 15)) * 80
                              + (kof + (lane >> 4) * 8) * 2;
                ldsm4(ah[mi], addr);
            }
            #pragma unroll
            for (int nip = 0; nip < 2; nip++) {
                uint32_t baddr = st + TILE_B
                               + (wn + nip * 16 + (lane & 7) + ((lane >> 4) << 3)) * 80
                               + (kof + ((lane >> 3) & 1) * 8) * 2;
                uint32_t bh[4], bl[4];
                ldsm4(bh, baddr);
                ldsm4(bl, baddr + TILE_B);
                #pragma unroll
                for (int mi = 0; mi < 2; mi++) {
                    mma16816(acc[mi][2 * nip],     ah[mi], bh[0], bh[1]);
                    mma16816(acc[mi][2 * nip],     ah[mi], bl[0], bl[1]);
                    mma16816(acc[mi][2 * nip + 1], ah[mi], bh[2], bh[3]);
                    mma16816(acc[mi][2 * nip + 1], ah[mi], bl[2], bl[3]);
                }
            }
        }
        __syncthreads();
    }

    // epilogue: bias + store
    #pragma unroll
    for (int mi = 0; mi < 2; mi++) {
        int row = bm + wm + mi * 16 + gid;
        #pragma unroll
        for (int ni = 0; ni < 4; ni++) {
            int col = bn + wn + ni * 8 + tig * 2;
            float b0 = bias[col], b1 = bias[col + 1];
            float2 r01 = make_float2(acc[mi][ni][0] + b0, acc[mi][ni][1] + b1);
            float2 r23 = make_float2(acc[mi][ni][2] + b0, acc[mi][ni][3] + b1);
            *reinterpret_cast<float2*>(&C[(size_t)row * GN + col])       = r01;
            *reinterpret_cast<float2*>(&C[(size_t)(row + 8) * GN + col]) = r23;
        }
    }
}

// ---------------------------------------------------------------------------
// Per-position attention. Reads g_Q/g_K/g_V; writes X as fp16 hi directly
// into A slot 0 ((B,H,S,D) layout = A operand of output projection).
// ---------------------------------------------------------------------------
__global__ __launch_bounds__(256) void attn_kernel(
    const float* __restrict__ SW, float* AT)
{
    const int p = blockIdx.x;
    const int b = p >> 12;
    const int s = p & 4095;
    const int tid = threadIdx.x;

    __shared__ __align__(16) float qs[16][65];
    __shared__ __align__(16) float ks_[16][65];
    __shared__ __align__(16) float vs[16][64];
    __shared__ float qn2[16], kn2[16];
    __shared__ float att[16][16];

    const size_t base = (size_t)p * 1024;
    {
        int e = tid * 4;
        int r = e >> 6, d = e & 63;
        float4 qv = *reinterpret_cast<const float4*>(g_Q + base + e);
        float4 kv = *reinterpret_cast<const float4*>(g_K + base + e);
        float4 vv = *reinterpret_cast<const float4*>(g_V + base + e);
        qs[r][d] = qv.x; qs[r][d + 1] = qv.y; qs[r][d + 2] = qv.z; qs[r][d + 3] = qv.w;
        ks_[r][d] = kv.x; ks_[r][d + 1] = kv.y; ks_[r][d + 2] = kv.z; ks_[r][d + 3] = kv.w;
        *reinterpret_cast<float4*>(&vs[r][d]) = vv;
    }
    float w0, w1, w2;
    {
        float s0 = SW[0], s1 = SW[1], s2 = SW[2];
        float mx = fmaxf(s0, fmaxf(s1, s2));
        float e0 = expf(s0 - mx), e1 = expf(s1 - mx), e2 = expf(s2 - mx);
        float inv = 1.f / (e0 + e1 + e2);
        w0 = e0 * inv; w1 = e1 * inv; w2 = e2 * inv;
    }
    __syncthreads();

    if (tid < 32) {
        int r = tid & 15;
        const float* src = (tid < 16) ? qs[r] : ks_[r];
        float ssum = 0.f;
        #pragma unroll 8
        for (int d = 0; d < 64; d++) ssum += src[d] * src[d];
        if (tid < 16) qn2[r] = ssum; else kn2[r] = ssum;
    }
    __syncthreads();

    {
        int i = tid >> 4, j = tid & 15;
        float qk = 0.f;
        #pragma unroll 8
        for (int d = 0; d < 64; d++) qk += qs[i][d] * ks_[j][d];
        float sq = qn2[i], sk = kn2[j];
        float dots  = qk * 0.125f;
        float denom = fmaxf(sqrtf(sq) * sqrtf(sk), 1e-8f);
        float cosv  = qk / denom;
        float d2    = fmaxf(sq + sk - 2.f * qk, 0.f);
        float dist  = -sqrtf(d2);
        float sc = w0 * dots + w1 * cosv + w2 * dist;

        float mx = sc;
        #pragma unroll
        for (int o = 8; o; o >>= 1) mx = fmaxf(mx, __shfl_xor_sync(0xffffffffu, mx, o, 16));
        float e = expf(sc - mx);
        float sm = e;
        #pragma unroll
        for (int o = 8; o; o >>= 1) sm += __shfl_xor_sync(0xffffffffu, sm, o, 16);
        float a = e / sm;
        att[i][j] = a;
        if (AT) AT[(size_t)p * 256 + tid] = a;
    }
    __syncthreads();

    {
        int i = tid >> 4, d0 = (tid & 15) * 4;
        float4 o = make_float4(0.f, 0.f, 0.f, 0.f);
        #pragma unroll
        for (int j = 0; j < 16; j++) {
            float a = att[i][j];
            float4 v4 = *reinterpret_cast<const float4*>(&vs[j][d0]);
            o.x += a * v4.x; o.y += a * v4.y; o.z += a * v4.z; o.w += a * v4.w;
        }
        size_t xidx = (size_t)b * 4194304 + (size_t)i * 262144 + (size_t)s * 64 + d0;
        __half2 h01 = __floats2half2_rn(o.x, o.y);
        __half2 h23 = __floats2half2_rn(o.z, o.w);
        uint2 hp = make_uint2(*reinterpret_cast<uint32_t*>(&h01),
                              *reinterpret_cast<uint32_t*>(&h23));
        *reinterpret_cast<uint2*>(&g_Ah[xidx]) = hp;   // slot 0
    }
}

// ---------------------------------------------------------------------------
// kernel_launch — 4th launch (profiled) is a GEMM.
// ---------------------------------------------------------------------------
extern "C" void kernel_launch(void* const* d_in, const int* in_sizes, int n_in,
                              void* d_out, int out_size) {
    (void)in_sizes; (void)n_in;
    const float* query = (const float*)d_in[0];
    const float* key   = (const float*)d_in[1];
    const float* value = (const float*)d_in[2];
    const float* Wq = (const float*)d_in[3];
    const float* bq = (const float*)d_in[4];
    const float* Wk = (const float*)d_in[5];
    const float* bk = (const float*)d_in[6];
    const float* Wv = (const float*)d_in[7];
    const float* bv = (const float*)d_in[8];
    const float* Wo = (const float*)d_in[9];
    const float* bo = (const float*)d_in[10];
    const float* sw = (const float*)d_in[11];
    float* out = (float*)d_out;

    static bool attr_set = false;
    if (!attr_set) {
        cudaFuncSetAttribute(gemm_tc_kernel,
                             cudaFuncAttributeMaxDynamicSharedMemorySize, GSMEM);
        attr_set = true;
    }

    dim3 ggrid(GN / 128, GM / 128);            // (8, 128)
    dim3 sagrid((GM * GK) / (256 * 4), 1, 3);  // (16384, 1, 3)
    dim3 swgrid(GN / 32, GK / 32, 4);          // (32, 32, 4)

    // 1: all A splits  2: all W^T splits
    split_a3_kernel<<<sagrid, 256>>>(query, key, value);
    split_wt4_kernel<<<swgrid, 256>>>(Wq, Wk, Wv, Wo);

    // 3,4,5: Q, K (profiled), V projections
    gemm_tc_kernel<<<ggrid, 512, GSMEM>>>(0, 0, nullptr, 1, bq);
    gemm_tc_kernel<<<ggrid, 512, GSMEM>>>(1, 1, nullptr, 2, bk);
    gemm_tc_kernel<<<ggrid, 512, GSMEM>>>(2, 2, nullptr, 3, bv);

    // 6: attention (writes X fp16 into slot 0)
    float* attn_dst = (out_size >= MAIN_OUT_ELEMS + ATT_ELEMS) ? (out + MAIN_OUT_ELEMS)
                                                               : nullptr;
    attn_kernel<<<NPOS, 256>>>(sw, attn_dst);

    // 7: output projection
    gemm_tc_kernel<<<ggrid, 512, GSMEM>>>(0, 3, out, 0, bo);
}

// round 10
// speedup vs baseline: 1.3883x; 1.0788x over previous
#include <cuda_runtime.h>
#include <cuda_fp16.h>
#include <stdint.h>

// Problem constants (B=4, S=4096, HID=1024, H=16, D=64)
#define GM 16384
#define GN 1024
#define GK 1024
#define NPOS 16384
#define ATT_ELEMS (NPOS * 256)
#define MAIN_OUT_ELEMS (GM * GN)
#define ASLOT ((size_t)GM * GK)
#define WSLOT ((size_t)GN * GK)

// Device-global scratch (no allocations allowed)
__device__ __align__(16) float g_Q[GM * GN];
__device__ __align__(16) float g_K[GM * GN];
__device__ __align__(16) float g_V[GM * GN];
// A-operand fp16 hi: slot 0 = query (later reused for X), 1 = key, 2 = value
__device__ __align__(16) __half g_Ah[3 * ASLOT];
// W^T fp16 hi/lo: slot 0..3 = Wq, Wk, Wv, Wo   ([n][k] layout)
__device__ __align__(16) __half g_Wth[4 * WSLOT];
__device__ __align__(16) __half g_Wtl[4 * WSLOT];

// ---------------------------------------------------------------------------
// helpers
// ---------------------------------------------------------------------------
__device__ __forceinline__ void mma16816(float* c, const uint32_t* a, uint32_t b0, uint32_t b1) {
    asm volatile(
        "mma.sync.aligned.m16n8k16.row.col.f32.f16.f16.f32 "
        "{%0,%1,%2,%3}, {%4,%5,%6,%7}, {%8,%9}, {%0,%1,%2,%3};"
        : "+f"(c[0]), "+f"(c[1]), "+f"(c[2]), "+f"(c[3])
        : "r"(a[0]), "r"(a[1]), "r"(a[2]), "r"(a[3]), "r"(b0), "r"(b1));
}

__device__ __forceinline__ void ldsm4(uint32_t* r, uint32_t addr) {
    asm volatile("ldmatrix.sync.aligned.m8n8.x4.shared.b16 {%0,%1,%2,%3}, [%4];"
                 : "=r"(r[0]), "=r"(r[1]), "=r"(r[2]), "=r"(r[3]) : "r"(addr));
}

__device__ __forceinline__ void cp16(uint32_t dst, const void* src) {
    asm volatile("cp.async.cg.shared.global [%0], [%1], 16;" :: "r"(dst), "l"(src));
}

// ---------------------------------------------------------------------------
// Split kernels
// ---------------------------------------------------------------------------
__global__ __launch_bounds__(256) void split_a3_kernel(
    const float* __restrict__ q, const float* __restrict__ k,
    const float* __restrict__ v)
{
    const int z = blockIdx.z;
    const float* A = (z == 0) ? q : (z == 1) ? k : v;
    size_t idx = (size_t)blockIdx.x * 256 + threadIdx.x;   // float4 index
    float4 vv = reinterpret_cast<const float4*>(A)[idx];
    __half2 h01 = __floats2half2_rn(vv.x, vv.y);
    __half2 h23 = __floats2half2_rn(vv.z, vv.w);
    __half2* Hp = reinterpret_cast<__half2*>(g_Ah + (size_t)z * ASLOT);
    Hp[idx * 2]     = h01;
    Hp[idx * 2 + 1] = h23;
}

__global__ __launch_bounds__(256) void split_wt4_kernel(
    const float* __restrict__ w0, const float* __restrict__ w1,
    const float* __restrict__ w2, const float* __restrict__ w3)
{
    const int z = blockIdx.z;
    const float* W = (z == 0) ? w0 : (z == 1) ? w1 : (z == 2) ? w2 : w3;
    __half* Wh = g_Wth + (size_t)z * WSLOT;
    __half* Wl = g_Wtl + (size_t)z * WSLOT;

    __shared__ float t[32][33];
    int n0 = blockIdx.x * 32, k0 = blockIdx.y * 32;
    int tx = threadIdx.x & 31, ty = threadIdx.x >> 5;
    #pragma unroll
    for (int j = 0; j < 4; j++)
        t[ty + 8 * j][tx] = W[(size_t)(k0 + ty + 8 * j) * GN + n0 + tx];
    __syncthreads();
    #pragma unroll
    for (int j = 0; j < 4; j++) {
        int r = ty + 8 * j;
        float v = t[tx][r];
        __half h = __float2half_rn(v);
        __half l = __float2half_rn(v - __half2float(h));
        Wh[(size_t)(n0 + r) * GK + k0 + tx] = h;
        Wl[(size_t)(n0 + r) * GK + k0 + tx] = l;
    }
}

// ---------------------------------------------------------------------------
// GEMM: C = A @ W + bias. A = fp16 hi; W = fp16 hi+lo (2-term compensated).
// CTA 128x128, BK=32, 256 threads = 8 warps (2x4), warp tile 64x32.
// MMA:LDSM = 4:1; bh/bl terms interleaved at distance 8 to hide HMMA RAW.
// ---------------------------------------------------------------------------
#define TILE_B   10240              // 128 rows * 80 B
#define STAGE_B  (3 * TILE_B)       // Ah, Bh, Bl
#define GSMEM    (2 * STAGE_B)      // 61440

__device__ __forceinline__ float* out_ptr(int tag) {
    switch (tag) { case 1: return g_Q; case 2: return g_K; default: return g_V; }
}

__global__ __launch_bounds__(256, 1) void gemm_tc_kernel(
    int a_slot, int w_slot, float* Cout, int c_tag, const float* __restrict__ bias)
{
    const __half* Ah = g_Ah + (size_t)a_slot * ASLOT;
    const __half* Bh = g_Wth + (size_t)w_slot * WSLOT;
    const __half* Bl = g_Wtl + (size_t)w_slot * WSLOT;
    float* C = Cout ? Cout : out_ptr(c_tag);

    extern __shared__ __align__(16) char sm[];
    const uint32_t smbase = (uint32_t)__cvta_generic_to_shared(sm);

    const int tid  = threadIdx.x;
    const int warp = tid >> 5;
    const int lane = tid & 31;
    const int gid  = lane >> 2;
    const int tig  = lane & 3;
    const int wm = (warp >> 2) * 64;    // 0 or 64
    const int wn = (warp & 3) * 32;     // 0,32,64,96
    const int bm = blockIdx.y * 128;
    const int bn = blockIdx.x * 128;

    // copy coords: 2 chunk-assignments per thread cover one 128x80B tile
    const int crow0 = tid >> 2, cch0 = (tid & 3);
    const int crow1 = (tid + 256) >> 2, cch1 = ((tid + 256) & 3);

    float acc[4][4][4];
    #pragma unroll
    for (int a = 0; a < 4; a++)
        #pragma unroll
        for (int b = 0; b < 4; b++)
            #pragma unroll
            for (int c = 0; c < 4; c++) acc[a][b][c] = 0.f;

    auto stage_copy = [&](int s, int kt) {
        uint32_t st = smbase + s * STAGE_B;
        const int kof = kt * 32;
        {
            uint32_t d = st + crow0 * 80 + cch0 * 16;
            cp16(d,              Ah + (size_t)(bm + crow0) * GK + kof + cch0 * 8);
            cp16(d + TILE_B,     Bh + (size_t)(bn + crow0) * GK + kof + cch0 * 8);
            cp16(d + 2 * TILE_B, Bl + (size_t)(bn + crow0) * GK + kof + cch0 * 8);
        }
        {
            uint32_t d = st + crow1 * 80 + cch1 * 16;
            cp16(d,              Ah + (size_t)(bm + crow1) * GK + kof + cch1 * 8);
            cp16(d + TILE_B,     Bh + (size_t)(bn + crow1) * GK + kof + cch1 * 8);
            cp16(d + 2 * TILE_B, Bl + (size_t)(bn + crow1) * GK + kof + cch1 * 8);
        }
        asm volatile("cp.async.commit_group;" ::: "memory");
    };

    stage_copy(0, 0);

    for (int kt = 0; kt < 32; kt++) {
        if (kt + 1 < 32) {
            stage_copy((kt + 1) & 1, kt + 1);
            asm volatile("cp.async.wait_group 1;" ::: "memory");
        } else {
            asm volatile("cp.async.wait_group 0;" ::: "memory");
        }
        __syncthreads();

        uint32_t st = smbase + (kt & 1) * STAGE_B;
        #pragma unroll
        for (int ks = 0; ks < 2; ks++) {
            const int kof = ks * 16;
            uint32_t ah[4][4];
            #pragma unroll
            for (int mi = 0; mi < 4; mi++) {
                uint32_t addr = st + (wm + mi * 16 + (lane & 15)) * 80
                              + (kof + (lane >> 4) * 8) * 2;
                ldsm4(ah[mi], addr);
            }
            #pragma unroll
            for (int nip = 0; nip < 2; nip++) {
                uint32_t baddr = st + TILE_B
                               + (wn + nip * 16 + (lane & 7) + ((lane >> 4) << 3)) * 80
                               + (kof + ((lane >> 3) & 1) * 8) * 2;
                uint32_t bh[4], bl[4];
                ldsm4(bh, baddr);
                ldsm4(bl, baddr + TILE_B);
                // bh term for all 8 accs, then bl term: RAW distance = 8 MMAs
                #pragma unroll
                for (int mi = 0; mi < 4; mi++) {
                    mma16816(acc[mi][2 * nip],     ah[mi], bh[0], bh[1]);
                    mma16816(acc[mi][2 * nip + 1], ah[mi], bh[2], bh[3]);
                }
                #pragma unroll
                for (int mi = 0; mi < 4; mi++) {
                    mma16816(acc[mi][2 * nip],     ah[mi], bl[0], bl[1]);
                    mma16816(acc[mi][2 * nip + 1], ah[mi], bl[2], bl[3]);
                }
            }
        }
        __syncthreads();
    }

    // epilogue: bias + store
    #pragma unroll
    for (int mi = 0; mi < 4; mi++) {
        int row = bm + wm + mi * 16 + gid;
        #pragma unroll
        for (int ni = 0; ni < 4; ni++) {
            int col = bn + wn + ni * 8 + tig * 2;
            float b0 = bias[col], b1 = bias[col + 1];
            float2 r01 = make_float2(acc[mi][ni][0] + b0, acc[mi][ni][1] + b1);
            float2 r23 = make_float2(acc[mi][ni][2] + b0, acc[mi][ni][3] + b1);
            *reinterpret_cast<float2*>(&C[(size_t)row * GN + col])       = r01;
            *reinterpret_cast<float2*>(&C[(size_t)(row + 8) * GN + col]) = r23;
        }
    }
}

// ---------------------------------------------------------------------------
// Per-position attention, float4 smem paths (17-float4 padded rows:
// conflict-free per 8-lane LDS.128 phase). Writes X fp16 into A slot 0.
// ---------------------------------------------------------------------------
__global__ __launch_bounds__(256) void attn_kernel(
    const float* __restrict__ SW, float* AT)
{
    const int p = blockIdx.x;
    const int b = p >> 12;
    const int s = p & 4095;
    const int tid = threadIdx.x;

    __shared__ __align__(16) float4 qs4[16][17];
    __shared__ __align__(16) float4 ks4[16][17];
    __shared__ __align__(16) float4 vs4[16][17];
    __shared__ float qn2[16], kn2[16];
    __shared__ float att[16][16];

    const size_t base = (size_t)p * 1024;
    const int r = tid >> 4, c = tid & 15;   // each thread: one float4 per tensor
    {
        size_t e = base + (size_t)tid * 4;
        qs4[r][c] = *reinterpret_cast<const float4*>(g_Q + e);
        ks4[r][c] = *reinterpret_cast<const float4*>(g_K + e);
        vs4[r][c] = *reinterpret_cast<const float4*>(g_V + e);
    }
    float w0, w1, w2;
    {
        float s0 = SW[0], s1 = SW[1], s2 = SW[2];
        float mx = fmaxf(s0, fmaxf(s1, s2));
        float e0 = expf(s0 - mx), e1 = expf(s1 - mx), e2 = expf(s2 - mx);
        float inv = 1.f / (e0 + e1 + e2);
        w0 = e0 * inv; w1 = e1 * inv; w2 = e2 * inv;
    }
    __syncthreads();

    // squared norms (32 threads, float4)
    if (tid < 32) {
        int rr = tid & 15;
        const float4* src = (tid < 16) ? qs4[rr] : ks4[rr];
        float ssum = 0.f;
        #pragma unroll
        for (int d = 0; d < 16; d++) {
            float4 v = src[d];
            ssum += v.x * v.x + v.y * v.y + v.z * v.z + v.w * v.w;
        }
        if (tid < 16) qn2[rr] = ssum; else kn2[rr] = ssum;
    }
    __syncthreads();

    // scores + softmax over j
    {
        int i = tid >> 4, j = tid & 15;
        float qk = 0.f;
        #pragma unroll
        for (int d = 0; d < 16; d++) {
            float4 a = qs4[i][d];
            float4 bv = ks4[j][d];
            qk += a.x * bv.x + a.y * bv.y + a.z * bv.z + a.w * bv.w;
        }
        float sq = qn2[i], sk = kn2[j];
        float dots  = qk * 0.125f;
        float denom = fmaxf(sqrtf(sq) * sqrtf(sk), 1e-8f);
        float cosv  = qk / denom;
        float d2    = fmaxf(sq + sk - 2.f * qk, 0.f);
        float dist  = -sqrtf(d2);
        float sc = w0 * dots + w1 * cosv + w2 * dist;

        float mx = sc;
        #pragma unroll
        for (int o = 8; o; o >>= 1) mx = fmaxf(mx, __shfl_xor_sync(0xffffffffu, mx, o, 16));
        float e = expf(sc - mx);
        float sm = e;
        #pragma unroll
        for (int o = 8; o; o >>= 1) sm += __shfl_xor_sync(0xffffffffu, sm, o, 16);
        float a = e / sm;
        att[i][j] = a;
        if (AT) AT[(size_t)p * 256 + tid] = a;
    }
    __syncthreads();

    // out[i][d] = sum_j att[i][j] * v[j][d]; fp16 X into slot 0 (B,H,S,D)
    {
        int i = tid >> 4, cc = tid & 15;
        float4 o = make_float4(0.f, 0.f, 0.f, 0.f);
        #pragma unroll
        for (int j = 0; j < 16; j++) {
            float a = att[i][j];
            float4 v4 = vs4[j][cc];
            o.x += a * v4.x; o.y += a * v4.y; o.z += a * v4.z; o.w += a * v4.w;
        }
        size_t xidx = (size_t)b * 4194304 + (size_t)i * 262144 + (size_t)s * 64 + cc * 4;
        __half2 h01 = __floats2half2_rn(o.x, o.y);
        __half2 h23 = __floats2half2_rn(o.z, o.w);
        uint2 hp = make_uint2(*reinterpret_cast<uint32_t*>(&h01),
                              *reinterpret_cast<uint32_t*>(&h23));
        *reinterpret_cast<uint2*>(&g_Ah[xidx]) = hp;   // slot 0
    }
}

// ---------------------------------------------------------------------------
// kernel_launch — 4th launch (profiled) is a GEMM.
// ---------------------------------------------------------------------------
extern "C" void kernel_launch(void* const* d_in, const int* in_sizes, int n_in,
                              void* d_out, int out_size) {
    (void)in_sizes; (void)n_in;
    const float* query = (const float*)d_in[0];
    const float* key   = (const float*)d_in[1];
    const float* value = (const float*)d_in[2];
    const float* Wq = (const float*)d_in[3];
    const float* bq = (const float*)d_in[4];
    const float* Wk = (const float*)d_in[5];
    const float* bk = (const float*)d_in[6];
    const float* Wv = (const float*)d_in[7];
    const float* bv = (const float*)d_in[8];
    const float* Wo = (const float*)d_in[9];
    const float* bo = (const float*)d_in[10];
    const float* sw = (const float*)d_in[11];
    float* out = (float*)d_out;

    static bool attr_set = false;
    if (!attr_set) {
        cudaFuncSetAttribute(gemm_tc_kernel,
                             cudaFuncAttributeMaxDynamicSharedMemorySize, GSMEM);
        attr_set = true;
    }

    dim3 ggrid(GN / 128, GM / 128);            // (8, 128)
    dim3 sagrid((GM * GK) / (256 * 4), 1, 3);  // (16384, 1, 3)
    dim3 swgrid(GN / 32, GK / 32, 4);          // (32, 32, 4)

    // 1: all A splits  2: all W^T splits
    split_a3_kernel<<<sagrid, 256>>>(query, key, value);
    split_wt4_kernel<<<swgrid, 256>>>(Wq, Wk, Wv, Wo);

    // 3,4,5: Q, K (profiled), V projections
    gemm_tc_kernel<<<ggrid, 256, GSMEM>>>(0, 0, nullptr, 1, bq);
    gemm_tc_kernel<<<ggrid, 256, GSMEM>>>(1, 1, nullptr, 2, bk);
    gemm_tc_kernel<<<ggrid, 256, GSMEM>>>(2, 2, nullptr, 3, bv);

    // 6: attention (writes X fp16 into slot 0)
    float* attn_dst = (out_size >= MAIN_OUT_ELEMS + ATT_ELEMS) ? (out + MAIN_OUT_ELEMS)
                                                               : nullptr;
    attn_kernel<<<NPOS, 256>>>(sw, attn_dst);

    // 7: output projection
    gemm_tc_kernel<<<ggrid, 256, GSMEM>>>(0, 3, out, 0, bo);
}

// round 11
// speedup vs baseline: 1.9872x; 1.4313x over previous
#include <cuda_runtime.h>
#include <cuda_fp16.h>
#include <stdint.h>

// Problem constants (B=4, S=4096, HID=1024, H=16, D=64)
#define GM 16384
#define GN 1024
#define GK 1024
#define NPOS 16384
#define ATT_ELEMS (NPOS * 256)
#define MAIN_OUT_ELEMS (GM * GN)
#define ASLOT ((size_t)GM * GK)
#define WSLOT ((size_t)GN * GK)

// Device-global scratch (no allocations allowed)
__device__ __align__(16) float g_Q[GM * GN];
__device__ __align__(16) float g_K[GM * GN];
__device__ __align__(16) float g_V[GM * GN];
// A-operand fp16: slot 0 = query (later reused for X), 1 = key, 2 = value
__device__ __align__(16) __half g_Ah[3 * ASLOT];
// W^T fp16: slot 0..3 = Wq, Wk, Wv, Wo   ([n][k] layout)
__device__ __align__(16) __half g_Wth[4 * WSLOT];

// ---------------------------------------------------------------------------
// helpers
// ---------------------------------------------------------------------------
__device__ __forceinline__ void mma16816(float* c, const uint32_t* a, uint32_t b0, uint32_t b1) {
    asm volatile(
        "mma.sync.aligned.m16n8k16.row.col.f32.f16.f16.f32 "
        "{%0,%1,%2,%3}, {%4,%5,%6,%7}, {%8,%9}, {%0,%1,%2,%3};"
        : "+f"(c[0]), "+f"(c[1]), "+f"(c[2]), "+f"(c[3])
        : "r"(a[0]), "r"(a[1]), "r"(a[2]), "r"(a[3]), "r"(b0), "r"(b1));
}

__device__ __forceinline__ void ldsm4(uint32_t* r, uint32_t addr) {
    asm volatile("ldmatrix.sync.aligned.m8n8.x4.shared.b16 {%0,%1,%2,%3}, [%4];"
                 : "=r"(r[0]), "=r"(r[1]), "=r"(r[2]), "=r"(r[3]) : "r"(addr));
}

__device__ __forceinline__ void cp16(uint32_t dst, const void* src) {
    asm volatile("cp.async.cg.shared.global [%0], [%1], 16;" :: "r"(dst), "l"(src));
}

// ---------------------------------------------------------------------------
// Split kernels
// ---------------------------------------------------------------------------
__global__ __launch_bounds__(256) void split_a3_kernel(
    const float* __restrict__ q, const float* __restrict__ k,
    const float* __restrict__ v)
{
    const int z = blockIdx.z;
    const float* A = (z == 0) ? q : (z == 1) ? k : v;
    size_t idx = (size_t)blockIdx.x * 256 + threadIdx.x;   // float4 index
    float4 vv = reinterpret_cast<const float4*>(A)[idx];
    __half2 h01 = __floats2half2_rn(vv.x, vv.y);
    __half2 h23 = __floats2half2_rn(vv.z, vv.w);
    __half2* Hp = reinterpret_cast<__half2*>(g_Ah + (size_t)z * ASLOT);
    Hp[idx * 2]     = h01;
    Hp[idx * 2 + 1] = h23;
}

// W fp32 [K,N] -> fp16 [N,K] (transpose). blockIdx.z selects W.
__global__ __launch_bounds__(256) void split_wt4_kernel(
    const float* __restrict__ w0, const float* __restrict__ w1,
    const float* __restrict__ w2, const float* __restrict__ w3)
{
    const int z = blockIdx.z;
    const float* W = (z == 0) ? w0 : (z == 1) ? w1 : (z == 2) ? w2 : w3;
    __half* Wh = g_Wth + (size_t)z * WSLOT;

    __shared__ float t[32][33];
    int n0 = blockIdx.x * 32, k0 = blockIdx.y * 32;
    int tx = threadIdx.x & 31, ty = threadIdx.x >> 5;
    #pragma unroll
    for (int j = 0; j < 4; j++)
        t[ty + 8 * j][tx] = W[(size_t)(k0 + ty + 8 * j) * GN + n0 + tx];
    __syncthreads();
    #pragma unroll
    for (int j = 0; j < 4; j++) {
        int r = ty + 8 * j;
        Wh[(size_t)(n0 + r) * GK + k0 + tx] = __float2half_rn(t[tx][r]);
    }
}

// ---------------------------------------------------------------------------
// GEMM: C = A @ W + bias. Plain fp16 operands, fp32 accumulate.
// CTA 128x128, BK=32, 256 threads = 8 warps (2x4), warp tile 64x32.
// 2-stage cp.async pipeline, ldmatrix fragments.
// ---------------------------------------------------------------------------
#define TILE_B   10240              // 128 rows * 80 B
#define STAGE_B  (2 * TILE_B)       // Ah, Bh
#define GSMEM    (2 * STAGE_B)      // 40960

__device__ __forceinline__ float* out_ptr(int tag) {
    switch (tag) { case 1: return g_Q; case 2: return g_K; default: return g_V; }
}

__global__ __launch_bounds__(256, 1) void gemm_tc_kernel(
    int a_slot, int w_slot, float* Cout, int c_tag, const float* __restrict__ bias)
{
    const __half* Ah = g_Ah + (size_t)a_slot * ASLOT;
    const __half* Bh = g_Wth + (size_t)w_slot * WSLOT;
    float* C = Cout ? Cout : out_ptr(c_tag);

    extern __shared__ __align__(16) char sm[];
    const uint32_t smbase = (uint32_t)__cvta_generic_to_shared(sm);

    const int tid  = threadIdx.x;
    const int warp = tid >> 5;
    const int lane = tid & 31;
    const int gid  = lane >> 2;
    const int tig  = lane & 3;
    const int wm = (warp >> 2) * 64;    // 0 or 64
    const int wn = (warp & 3) * 32;     // 0,32,64,96
    const int bm = blockIdx.y * 128;
    const int bn = blockIdx.x * 128;

    // copy coords: 2 chunk-assignments per thread cover one 128x80B tile
    const int crow0 = tid >> 2, cch0 = (tid & 3);
    const int crow1 = (tid + 256) >> 2, cch1 = ((tid + 256) & 3);

    float acc[4][4][4];
    #pragma unroll
    for (int a = 0; a < 4; a++)
        #pragma unroll
        for (int b = 0; b < 4; b++)
            #pragma unroll
            for (int c = 0; c < 4; c++) acc[a][b][c] = 0.f;

    auto stage_copy = [&](int s, int kt) {
        uint32_t st = smbase + s * STAGE_B;
        const int kof = kt * 32;
        {
            uint32_t d = st + crow0 * 80 + cch0 * 16;
            cp16(d,          Ah + (size_t)(bm + crow0) * GK + kof + cch0 * 8);
            cp16(d + TILE_B, Bh + (size_t)(bn + crow0) * GK + kof + cch0 * 8);
        }
        {
            uint32_t d = st + crow1 * 80 + cch1 * 16;
            cp16(d,          Ah + (size_t)(bm + crow1) * GK + kof + cch1 * 8);
            cp16(d + TILE_B, Bh + (size_t)(bn + crow1) * GK + kof + cch1 * 8);
        }
        asm volatile("cp.async.commit_group;" ::: "memory");
    };

    stage_copy(0, 0);

    for (int kt = 0; kt < 32; kt++) {
        if (kt + 1 < 32) {
            stage_copy((kt + 1) & 1, kt + 1);
            asm volatile("cp.async.wait_group 1;" ::: "memory");
        } else {
            asm volatile("cp.async.wait_group 0;" ::: "memory");
        }
        __syncthreads();

        uint32_t st = smbase + (kt & 1) * STAGE_B;
        #pragma unroll
        for (int ks = 0; ks < 2; ks++) {
            const int kof = ks * 16;
            uint32_t ah[4][4];
            #pragma unroll
            for (int mi = 0; mi < 4; mi++) {
                uint32_t addr = st + (wm + mi * 16 + (lane & 15)) * 80
                              + (kof + (lane >> 4) * 8) * 2;
                ldsm4(ah[mi], addr);
            }
            #pragma unroll
            for (int nip = 0; nip < 2; nip++) {
                uint32_t baddr = st + TILE_B
                               + (wn + nip * 16 + (lane & 7) + ((lane >> 4) << 3)) * 80
                               + (kof + ((lane >> 3) & 1) * 8) * 2;
                uint32_t bh[4];
                ldsm4(bh, baddr);
                #pragma unroll
                for (int mi = 0; mi < 4; mi++) {
                    mma16816(acc[mi][2 * nip],     ah[mi], bh[0], bh[1]);
                    mma16816(acc[mi][2 * nip + 1], ah[mi], bh[2], bh[3]);
                }
            }
        }
        __syncthreads();
    }

    // epilogue: bias + store
    #pragma unroll
    for (int mi = 0; mi < 4; mi++) {
        int row = bm + wm + mi * 16 + gid;
        #pragma unroll
        for (int ni = 0; ni < 4; ni++) {
            int col = bn + wn + ni * 8 + tig * 2;
            float b0 = bias[col], b1 = bias[col + 1];
            float2 r01 = make_float2(acc[mi][ni][0] + b0, acc[mi][ni][1] + b1);
            float2 r23 = make_float2(acc[mi][ni][2] + b0, acc[mi][ni][3] + b1);
            *reinterpret_cast<float2*>(&C[(size_t)row * GN + col])       = r01;
            *reinterpret_cast<float2*>(&C[(size_t)(row + 8) * GN + col]) = r23;
        }
    }
}

// ---------------------------------------------------------------------------
// Per-position attention, float4 smem paths. Writes X fp16 into A slot 0.
// ---------------------------------------------------------------------------
__global__ __launch_bounds__(256) void attn_kernel(
    const float* __restrict__ SW, float* AT)
{
    const int p = blockIdx.x;
    const int b = p >> 12;
    const int s = p & 4095;
    const int tid = threadIdx.x;

    __shared__ __align__(16) float4 qs4[16][17];
    __shared__ __align__(16) float4 ks4[16][17];
    __shared__ __align__(16) float4 vs4[16][17];
    __shared__ float qn2[16], kn2[16];
    __shared__ float att[16][16];

    const size_t base = (size_t)p * 1024;
    const int r = tid >> 4, c = tid & 15;
    {
        size_t e = base + (size_t)tid * 4;
        qs4[r][c] = *reinterpret_cast<const float4*>(g_Q + e);
        ks4[r][c] = *reinterpret_cast<const float4*>(g_K + e);
        vs4[r][c] = *reinterpret_cast<const float4*>(g_V + e);
    }
    float w0, w1, w2;
    {
        float s0 = SW[0], s1 = SW[1], s2 = SW[2];
        float mx = fmaxf(s0, fmaxf(s1, s2));
        float e0 = expf(s0 - mx), e1 = expf(s1 - mx), e2 = expf(s2 - mx);
        float inv = 1.f / (e0 + e1 + e2);
        w0 = e0 * inv; w1 = e1 * inv; w2 = e2 * inv;
    }
    __syncthreads();

    if (tid < 32) {
        int rr = tid & 15;
        const float4* src = (tid < 16) ? qs4[rr] : ks4[rr];
        float ssum = 0.f;
        #pragma unroll
        for (int d = 0; d < 16; d++) {
            float4 v = src[d];
            ssum += v.x * v.x + v.y * v.y + v.z * v.z + v.w * v.w;
        }
        if (tid < 16) qn2[rr] = ssum; else kn2[rr] = ssum;
    }
    __syncthreads();

    {
        int i = tid >> 4, j = tid & 15;
        float qk = 0.f;
        #pragma unroll
        for (int d = 0; d < 16; d++) {
            float4 a = qs4[i][d];
            float4 bv = ks4[j][d];
            qk += a.x * bv.x + a.y * bv.y + a.z * bv.z + a.w * bv.w;
        }
        float sq = qn2[i], sk = kn2[j];
        float dots  = qk * 0.125f;
        float denom = fmaxf(sqrtf(sq) * sqrtf(sk), 1e-8f);
        float cosv  = qk / denom;
        float d2    = fmaxf(sq + sk - 2.f * qk, 0.f);
        float dist  = -sqrtf(d2);
        float sc = w0 * dots + w1 * cosv + w2 * dist;

        float mx = sc;
        #pragma unroll
        for (int o = 8; o; o >>= 1) mx = fmaxf(mx, __shfl_xor_sync(0xffffffffu, mx, o, 16));
        float e = expf(sc - mx);
        float sm = e;
        #pragma unroll
        for (int o = 8; o; o >>= 1) sm += __shfl_xor_sync(0xffffffffu, sm, o, 16);
        float a = e / sm;
        att[i][j] = a;
        if (AT) AT[(size_t)p * 256 + tid] = a;
    }
    __syncthreads();

    {
        int i = tid >> 4, cc = tid & 15;
        float4 o = make_float4(0.f, 0.f, 0.f, 0.f);
        #pragma unroll
        for (int j = 0; j < 16; j++) {
            float a = att[i][j];
            float4 v4 = vs4[j][cc];
            o.x += a * v4.x; o.y += a * v4.y; o.z += a * v4.z; o.w += a * v4.w;
        }
        size_t xidx = (size_t)b * 4194304 + (size_t)i * 262144 + (size_t)s * 64 + cc * 4;
        __half2 h01 = __floats2half2_rn(o.x, o.y);
        __half2 h23 = __floats2half2_rn(o.z, o.w);
        uint2 hp = make_uint2(*reinterpret_cast<uint32_t*>(&h01),
                              *reinterpret_cast<uint32_t*>(&h23));
        *reinterpret_cast<uint2*>(&g_Ah[xidx]) = hp;   // slot 0
    }
}

// ---------------------------------------------------------------------------
// kernel_launch — 4th launch (profiled) is a GEMM.
// ---------------------------------------------------------------------------
extern "C" void kernel_launch(void* const* d_in, const int* in_sizes, int n_in,
                              void* d_out, int out_size) {
    (void)in_sizes; (void)n_in;
    const float* query = (const float*)d_in[0];
    const float* key   = (const float*)d_in[1];
    const float* value = (const float*)d_in[2];
    const float* Wq = (const float*)d_in[3];
    const float* bq = (const float*)d_in[4];
    const float* Wk = (const float*)d_in[5];
    const float* bk = (const float*)d_in[6];
    const float* Wv = (const float*)d_in[7];
    const float* bv = (const float*)d_in[8];
    const float* Wo = (const float*)d_in[9];
    const float* bo = (const float*)d_in[10];
    const float* sw = (const float*)d_in[11];
    float* out = (float*)d_out;

    static bool attr_set = false;
    if (!attr_set) {
        cudaFuncSetAttribute(gemm_tc_kernel,
                             cudaFuncAttributeMaxDynamicSharedMemorySize, GSMEM);
        attr_set = true;
    }

    dim3 ggrid(GN / 128, GM / 128);            // (8, 128)
    dim3 sagrid((GM * GK) / (256 * 4), 1, 3);  // (16384, 1, 3)
    dim3 swgrid(GN / 32, GK / 32, 4);          // (32, 32, 4)

    // 1: all A splits  2: all W^T splits
    split_a3_kernel<<<sagrid, 256>>>(query, key, value);
    split_wt4_kernel<<<swgrid, 256>>>(Wq, Wk, Wv, Wo);

    // 3,4,5: Q, K (profiled), V projections
    gemm_tc_kernel<<<ggrid, 256, GSMEM>>>(0, 0, nullptr, 1, bq);
    gemm_tc_kernel<<<ggrid, 256, GSMEM>>>(1, 1, nullptr, 2, bk);
    gemm_tc_kernel<<<ggrid, 256, GSMEM>>>(2, 2, nullptr, 3, bv);

    // 6: attention (writes X fp16 into slot 0)
    float* attn_dst = (out_size >= MAIN_OUT_ELEMS + ATT_ELEMS) ? (out + MAIN_OUT_ELEMS)
                                                               : nullptr;
    attn_kernel<<<NPOS, 256>>>(sw, attn_dst);

    // 7: output projection
    gemm_tc_kernel<<<ggrid, 256, GSMEM>>>(0, 3, out, 0, bo);
}

// round 12
// speedup vs baseline: 2.2178x; 1.1161x over previous
#include <cuda_runtime.h>
#include <cuda_fp16.h>
#include <stdint.h>

// Problem constants (B=4, S=4096, HID=1024, H=16, D=64)
#define GM 16384
#define GN 1024
#define GK 1024
#define NPOS 16384
#define ATT_ELEMS (NPOS * 256)
#define MAIN_OUT_ELEMS (GM * GN)
#define ASLOT ((size_t)GM * GK)
#define WSLOT ((size_t)GN * GK)

// Device-global scratch (no allocations allowed)
__device__ __align__(16) float g_Q[GM * GN];
__device__ __align__(16) float g_K[GM * GN];
__device__ __align__(16) float g_V[GM * GN];
// A-operand fp16: slot 0 = query (later reused for X), 1 = key, 2 = value
__device__ __align__(16) __half g_Ah[3 * ASLOT];
// W^T fp16: slot 0..3 = Wq, Wk, Wv, Wo   ([n][k] layout)
__device__ __align__(16) __half g_Wth[4 * WSLOT];

// ---------------------------------------------------------------------------
// helpers
// ---------------------------------------------------------------------------
__device__ __forceinline__ void mma16816(float* c, const uint32_t* a, uint32_t b0, uint32_t b1) {
    asm volatile(
        "mma.sync.aligned.m16n8k16.row.col.f32.f16.f16.f32 "
        "{%0,%1,%2,%3}, {%4,%5,%6,%7}, {%8,%9}, {%0,%1,%2,%3};"
        : "+f"(c[0]), "+f"(c[1]), "+f"(c[2]), "+f"(c[3])
        : "r"(a[0]), "r"(a[1]), "r"(a[2]), "r"(a[3]), "r"(b0), "r"(b1));
}

__device__ __forceinline__ void ldsm4(uint32_t* r, uint32_t addr) {
    asm volatile("ldmatrix.sync.aligned.m8n8.x4.shared.b16 {%0,%1,%2,%3}, [%4];"
                 : "=r"(r[0]), "=r"(r[1]), "=r"(r[2]), "=r"(r[3]) : "r"(addr));
}

__device__ __forceinline__ void cp16(uint32_t dst, const void* src) {
    asm volatile("cp.async.cg.shared.global [%0], [%1], 16;" :: "r"(dst), "l"(src));
}

// ---------------------------------------------------------------------------
// Split kernels
// ---------------------------------------------------------------------------
__global__ __launch_bounds__(256) void split_a3_kernel(
    const float* __restrict__ q, const float* __restrict__ k,
    const float* __restrict__ v)
{
    const int z = blockIdx.z;
    const float* A = (z == 0) ? q : (z == 1) ? k : v;
    size_t idx = (size_t)blockIdx.x * 256 + threadIdx.x;   // float4 index
    float4 vv = reinterpret_cast<const float4*>(A)[idx];
    __half2 h01 = __floats2half2_rn(vv.x, vv.y);
    __half2 h23 = __floats2half2_rn(vv.z, vv.w);
    __half2* Hp = reinterpret_cast<__half2*>(g_Ah + (size_t)z * ASLOT);
    Hp[idx * 2]     = h01;
    Hp[idx * 2 + 1] = h23;
}

// W fp32 [K,N] -> fp16 [N,K] (transpose). blockIdx.z selects W.
__global__ __launch_bounds__(256) void split_wt4_kernel(
    const float* __restrict__ w0, const float* __restrict__ w1,
    const float* __restrict__ w2, const float* __restrict__ w3)
{
    const int z = blockIdx.z;
    const float* W = (z == 0) ? w0 : (z == 1) ? w1 : (z == 2) ? w2 : w3;
    __half* Wh = g_Wth + (size_t)z * WSLOT;

    __shared__ float t[32][33];
    int n0 = blockIdx.x * 32, k0 = blockIdx.y * 32;
    int tx = threadIdx.x & 31, ty = threadIdx.x >> 5;
    #pragma unroll
    for (int j = 0; j < 4; j++)
        t[ty + 8 * j][tx] = W[(size_t)(k0 + ty + 8 * j) * GN + n0 + tx];
    __syncthreads();
    #pragma unroll
    for (int j = 0; j < 4; j++) {
        int r = ty + 8 * j;
        Wh[(size_t)(n0 + r) * GK + k0 + tx] = __float2half_rn(t[tx][r]);
    }
}

// ---------------------------------------------------------------------------
// GEMM: C = A @ W + bias. Plain fp16 operands, fp32 accumulate.
// CTA 128x128, BK=64, 256 threads = 8 warps (2x4), warp tile 64x32.
// 2-stage cp.async pipeline, ONE __syncthreads per k-tile (16 total),
// next-stage copy issued before compute for full overlap.
// smem rows: 128B data + 16B pad (stride 144) -> conflict-free ldmatrix.
// ---------------------------------------------------------------------------
#define ROWB     144                 // bytes per smem row
#define TILE_B   (128 * ROWB)        // 18432
#define STAGE_B  (2 * TILE_B)        // A, B tiles
#define GSMEM    (2 * STAGE_B)       // 73728
#define NKT      16                  // GK / 64

__device__ __forceinline__ float* out_ptr(int tag) {
    switch (tag) { case 1: return g_Q; case 2: return g_K; default: return g_V; }
}

__global__ __launch_bounds__(256, 1) void gemm_tc_kernel(
    int a_slot, int w_slot, float* Cout, int c_tag, const float* __restrict__ bias)
{
    const __half* Ah = g_Ah + (size_t)a_slot * ASLOT;
    const __half* Bh = g_Wth + (size_t)w_slot * WSLOT;
    float* C = Cout ? Cout : out_ptr(c_tag);

    extern __shared__ __align__(16) char sm[];
    const uint32_t smbase = (uint32_t)__cvta_generic_to_shared(sm);

    const int tid  = threadIdx.x;
    const int warp = tid >> 5;
    const int lane = tid & 31;
    const int gid  = lane >> 2;
    const int tig  = lane & 3;
    const int wm = (warp >> 2) * 64;    // 0 or 64
    const int wn = (warp & 3) * 32;     // 0,32,64,96
    const int bm = blockIdx.y * 128;
    const int bn = blockIdx.x * 128;

    float acc[4][4][4];
    #pragma unroll
    for (int a = 0; a < 4; a++)
        #pragma unroll
        for (int b = 0; b < 4; b++)
            #pragma unroll
            for (int c = 0; c < 4; c++) acc[a][b][c] = 0.f;

    // one stage: A 128x64 fp16 + B 128x64 fp16; 8 cp16 per thread
    auto stage_copy = [&](int s, int kt) {
        uint32_t st = smbase + s * STAGE_B;
        const int kof = kt * 64;
        #pragma unroll
        for (int i = 0; i < 4; i++) {
            int q = tid + i * 256;        // 0..1023
            int r = q >> 3, ch = q & 7;   // row 0..127, chunk 0..7 (16B each)
            uint32_t d = st + r * ROWB + ch * 16;
            cp16(d,          Ah + (size_t)(bm + r) * GK + kof + ch * 8);
            cp16(d + TILE_B, Bh + (size_t)(bn + r) * GK + kof + ch * 8);
        }
        asm volatile("cp.async.commit_group;" ::: "memory");
    };

    stage_copy(0, 0);

    for (int kt = 0; kt < NKT; kt++) {
        asm volatile("cp.async.wait_group 0;" ::: "memory");
        __syncthreads();                      // stage kt ready; buf (kt+1)&1 free
        if (kt + 1 < NKT) stage_copy((kt + 1) & 1, kt + 1);   // overlaps compute

        uint32_t st = smbase + (kt & 1) * STAGE_B;
        #pragma unroll
        for (int ks = 0; ks < 4; ks++) {
            const int kof = ks * 16;
            uint32_t ah[4][4];
            #pragma unroll
            for (int mi = 0; mi < 4; mi++) {
                uint32_t addr = st + (wm + mi * 16 + (lane & 15)) * ROWB
                              + (kof + (lane >> 4) * 8) * 2;
                ldsm4(ah[mi], addr);
            }
            #pragma unroll
            for (int nip = 0; nip < 2; nip++) {
                uint32_t baddr = st + TILE_B
                               + (wn + nip * 16 + (lane & 7) + ((lane >> 4) << 3)) * ROWB
                               + (kof + ((lane >> 3) & 1) * 8) * 2;
                uint32_t bh[4];
                ldsm4(bh, baddr);
                #pragma unroll
                for (int mi = 0; mi < 4; mi++) {
                    mma16816(acc[mi][2 * nip],     ah[mi], bh[0], bh[1]);
                    mma16816(acc[mi][2 * nip + 1], ah[mi], bh[2], bh[3]);
                }
            }
        }
    }

    // epilogue: bias + store
    #pragma unroll
    for (int mi = 0; mi < 4; mi++) {
        int row = bm + wm + mi * 16 + gid;
        #pragma unroll
        for (int ni = 0; ni < 4; ni++) {
            int col = bn + wn + ni * 8 + tig * 2;
            float b0 = bias[col], b1 = bias[col + 1];
            float2 r01 = make_float2(acc[mi][ni][0] + b0, acc[mi][ni][1] + b1);
            float2 r23 = make_float2(acc[mi][ni][2] + b0, acc[mi][ni][3] + b1);
            *reinterpret_cast<float2*>(&C[(size_t)row * GN + col])       = r01;
            *reinterpret_cast<float2*>(&C[(size_t)(row + 8) * GN + col]) = r23;
        }
    }
}

// ---------------------------------------------------------------------------
// Per-position attention, float4 smem paths. Writes X fp16 into A slot 0.
// ---------------------------------------------------------------------------
__global__ __launch_bounds__(256) void attn_kernel(
    const float* __restrict__ SW, float* AT)
{
    const int p = blockIdx.x;
    const int b = p >> 12;
    const int s = p & 4095;
    const int tid = threadIdx.x;

    __shared__ __align__(16) float4 qs4[16][17];
    __shared__ __align__(16) float4 ks4[16][17];
    __shared__ __align__(16) float4 vs4[16][17];
    __shared__ float qn2[16], kn2[16];
    __shared__ float att[16][16];

    const size_t base = (size_t)p * 1024;
    const int r = tid >> 4, c = tid & 15;
    {
        size_t e = base + (size_t)tid * 4;
        qs4[r][c] = *reinterpret_cast<const float4*>(g_Q + e);
        ks4[r][c] = *reinterpret_cast<const float4*>(g_K + e);
        vs4[r][c] = *reinterpret_cast<const float4*>(g_V + e);
    }
    float w0, w1, w2;
    {
        float s0 = SW[0], s1 = SW[1], s2 = SW[2];
        float mx = fmaxf(s0, fmaxf(s1, s2));
        float e0 = expf(s0 - mx), e1 = expf(s1 - mx), e2 = expf(s2 - mx);
        float inv = 1.f / (e0 + e1 + e2);
        w0 = e0 * inv; w1 = e1 * inv; w2 = e2 * inv;
    }
    __syncthreads();

    if (tid < 32) {
        int rr = tid & 15;
        const float4* src = (tid < 16) ? qs4[rr] : ks4[rr];
        float ssum = 0.f;
        #pragma unroll
        for (int d = 0; d < 16; d++) {
            float4 v = src[d];
            ssum += v.x * v.x + v.y * v.y + v.z * v.z + v.w * v.w;
        }
        if (tid < 16) qn2[rr] = ssum; else kn2[rr] = ssum;
    }
    __syncthreads();

    {
        int i = tid >> 4, j = tid & 15;
        float qk = 0.f;
        #pragma unroll
        for (int d = 0; d < 16; d++) {
            float4 a = qs4[i][d];
            float4 bv = ks4[j][d];
            qk += a.x * bv.x + a.y * bv.y + a.z * bv.z + a.w * bv.w;
        }
        float sq = qn2[i], sk = kn2[j];
        float dots  = qk * 0.125f;
        float denom = fmaxf(sqrtf(sq) * sqrtf(sk), 1e-8f);
        float cosv  = qk / denom;
        float d2    = fmaxf(sq + sk - 2.f * qk, 0.f);
        float dist  = -sqrtf(d2);
        float sc = w0 * dots + w1 * cosv + w2 * dist;

        float mx = sc;
        #pragma unroll
        for (int o = 8; o; o >>= 1) mx = fmaxf(mx, __shfl_xor_sync(0xffffffffu, mx, o, 16));
        float e = expf(sc - mx);
        float sm = e;
        #pragma unroll
        for (int o = 8; o; o >>= 1) sm += __shfl_xor_sync(0xffffffffu, sm, o, 16);
        float a = e / sm;
        att[i][j] = a;
        if (AT) AT[(size_t)p * 256 + tid] = a;
    }
    __syncthreads();

    {
        int i = tid >> 4, cc = tid & 15;
        float4 o = make_float4(0.f, 0.f, 0.f, 0.f);
        #pragma unroll
        for (int j = 0; j < 16; j++) {
            float a = att[i][j];
            float4 v4 = vs4[j][cc];
            o.x += a * v4.x; o.y += a * v4.y; o.z += a * v4.z; o.w += a * v4.w;
        }
        size_t xidx = (size_t)b * 4194304 + (size_t)i * 262144 + (size_t)s * 64 + cc * 4;
        __half2 h01 = __floats2half2_rn(o.x, o.y);
        __half2 h23 = __floats2half2_rn(o.z, o.w);
        uint2 hp = make_uint2(*reinterpret_cast<uint32_t*>(&h01),
                              *reinterpret_cast<uint32_t*>(&h23));
        *reinterpret_cast<uint2*>(&g_Ah[xidx]) = hp;   // slot 0
    }
}

// ---------------------------------------------------------------------------
// kernel_launch — 4th launch (profiled) is a GEMM.
// ---------------------------------------------------------------------------
extern "C" void kernel_launch(void* const* d_in, const int* in_sizes, int n_in,
                              void* d_out, int out_size) {
    (void)in_sizes; (void)n_in;
    const float* query = (const float*)d_in[0];
    const float* key   = (const float*)d_in[1];
    const float* value = (const float*)d_in[2];
    const float* Wq = (const float*)d_in[3];
    const float* bq = (const float*)d_in[4];
    const float* Wk = (const float*)d_in[5];
    const float* bk = (const float*)d_in[6];
    const float* Wv = (const float*)d_in[7];
    const float* bv = (const float*)d_in[8];
    const float* Wo = (const float*)d_in[9];
    const float* bo = (const float*)d_in[10];
    const float* sw = (const float*)d_in[11];
    float* out = (float*)d_out;

    static bool attr_set = false;
    if (!attr_set) {
        cudaFuncSetAttribute(gemm_tc_kernel,
                             cudaFuncAttributeMaxDynamicSharedMemorySize, GSMEM);
        attr_set = true;
    }

    dim3 ggrid(GN / 128, GM / 128);            // (8, 128)
    dim3 sagrid((GM * GK) / (256 * 4), 1, 3);  // (16384, 1, 3)
    dim3 swgrid(GN / 32, GK / 32, 4);          // (32, 32, 4)

    // 1: all A splits  2: all W^T splits
    split_a3_kernel<<<sagrid, 256>>>(query, key, value);
    split_wt4_kernel<<<swgrid, 256>>>(Wq, Wk, Wv, Wo);

    // 3,4,5: Q, K (profiled), V projections
    gemm_tc_kernel<<<ggrid, 256, GSMEM>>>(0, 0, nullptr, 1, bq);
    gemm_tc_kernel<<<ggrid, 256, GSMEM>>>(1, 1, nullptr, 2, bk);
    gemm_tc_kernel<<<ggrid, 256, GSMEM>>>(2, 2, nullptr, 3, bv);

    // 6: attention (writes X fp16 into slot 0)
    float* attn_dst = (out_size >= MAIN_OUT_ELEMS + ATT_ELEMS) ? (out + MAIN_OUT_ELEMS)
                                                               : nullptr;
    attn_kernel<<<NPOS, 256>>>(sw, attn_dst);

    // 7: output projection
    gemm_tc_kernel<<<ggrid, 256, GSMEM>>>(0, 3, out, 0, bo);
}

// round 13
// speedup vs baseline: 2.3689x; 1.0681x over previous
#include <cuda_runtime.h>
#include <cuda_fp16.h>
#include <stdint.h>

// Problem constants (B=4, S=4096, HID=1024, H=16, D=64)
#define GM 16384
#define GN 1024
#define GK 1024
#define NPOS 16384
#define ATT_ELEMS (NPOS * 256)
#define MAIN_OUT_ELEMS (GM * GN)
#define WSLOT ((size_t)GN * GK)

// Device-global scratch (no allocations allowed)
__device__ __align__(16) float g_Q[GM * GN];
__device__ __align__(16) float g_K[GM * GN];
__device__ __align__(16) float g_V[GM * GN];
// X (attn output) as fp16, (B,H,S,D) layout = A operand of output projection
__device__ __align__(16) __half g_Xh[(size_t)GM * GK];
// W^T fp16: slot 0..3 = Wq, Wk, Wv, Wo   ([n][k] layout)
__device__ __align__(16) __half g_Wth[4 * WSLOT];

// ---------------------------------------------------------------------------
// helpers
// ---------------------------------------------------------------------------
__device__ __forceinline__ void mma16816(float* c, const uint32_t* a, uint32_t b0, uint32_t b1) {
    asm volatile(
        "mma.sync.aligned.m16n8k16.row.col.f32.f16.f16.f32 "
        "{%0,%1,%2,%3}, {%4,%5,%6,%7}, {%8,%9}, {%0,%1,%2,%3};"
        : "+f"(c[0]), "+f"(c[1]), "+f"(c[2]), "+f"(c[3])
        : "r"(a[0]), "r"(a[1]), "r"(a[2]), "r"(a[3]), "r"(b0), "r"(b1));
}

__device__ __forceinline__ void ldsm4(uint32_t* r, uint32_t addr) {
    asm volatile("ldmatrix.sync.aligned.m8n8.x4.shared.b16 {%0,%1,%2,%3}, [%4];"
                 : "=r"(r[0]), "=r"(r[1]), "=r"(r[2]), "=r"(r[3]) : "r"(addr));
}

__device__ __forceinline__ void cp16(uint32_t dst, const void* src) {
    asm volatile("cp.async.cg.shared.global [%0], [%1], 16;" :: "r"(dst), "l"(src));
}

__device__ __forceinline__ uint32_t h2u(__half2 h) { return *reinterpret_cast<uint32_t*>(&h); }

// ---------------------------------------------------------------------------
// W split: fp32 [K,N] -> fp16 [N,K] (transpose). blockIdx.z selects W.
// ---------------------------------------------------------------------------
__global__ __launch_bounds__(256) void split_wt4_kernel(
    const float* __restrict__ w0, const float* __restrict__ w1,
    const float* __restrict__ w2, const float* __restrict__ w3)
{
    const int z = blockIdx.z;
    const float* W = (z == 0) ? w0 : (z == 1) ? w1 : (z == 2) ? w2 : w3;
    __half* Wh = g_Wth + (size_t)z * WSLOT;

    __shared__ float t[32][33];
    int n0 = blockIdx.x * 32, k0 = blockIdx.y * 32;
    int tx = threadIdx.x & 31, ty = threadIdx.x >> 5;
    #pragma unroll
    for (int j = 0; j < 4; j++)
        t[ty + 8 * j][tx] = W[(size_t)(k0 + ty + 8 * j) * GN + n0 + tx];
    __syncthreads();
    #pragma unroll
    for (int j = 0; j < 4; j++) {
        int r = ty + 8 * j;
        Wh[(size_t)(n0 + r) * GK + k0 + tx] = __float2half_rn(t[tx][r]);
    }
}

// ---------------------------------------------------------------------------
// GEMM: C = A @ W + bias. fp16 MMA operands, fp32 accumulate.
// A path: fp32 (Afp32 != null, converted inline; LDG overlapped with compute)
//         or fp16 from g_Xh (Afp32 == null).
// CTA 128x128, BK=64, 256 threads = 8 warps (2x4), warp tile 64x32.
// 2-stage pipeline, one __syncthreads per k-tile.
// ---------------------------------------------------------------------------
#define ROWB     144                 // bytes per smem row (128 data + 16 pad)
#define TILE_B   (128 * ROWB)        // 18432
#define STAGE_B  (2 * TILE_B)        // A + B tiles
#define GSMEM    (2 * STAGE_B)       // 73728
#define NKT      16                  // GK / 64

__device__ __forceinline__ float* out_ptr(int tag) {
    switch (tag) { case 1: return g_Q; case 2: return g_K; default: return g_V; }
}

__global__ __launch_bounds__(256, 1) void gemm_tc_kernel(
    const float* __restrict__ Afp32, int w_slot,
    float* Cout, int c_tag, const float* __restrict__ bias)
{
    const __half* Bh = g_Wth + (size_t)w_slot * WSLOT;
    float* C = Cout ? Cout : out_ptr(c_tag);

    extern __shared__ __align__(16) char sm[];
    const uint32_t smbase = (uint32_t)__cvta_generic_to_shared(sm);

    const int tid  = threadIdx.x;
    const int warp = tid >> 5;
    const int lane = tid & 31;
    const int gid  = lane >> 2;
    const int tig  = lane & 3;
    const int wm = (warp >> 2) * 64;    // 0 or 64
    const int wn = (warp & 3) * 32;     // 0,32,64,96
    const int bm = blockIdx.y * 128;
    const int bn = blockIdx.x * 128;

    float acc[4][4][4];
    #pragma unroll
    for (int a = 0; a < 4; a++)
        #pragma unroll
        for (int b = 0; b < 4; b++)
            #pragma unroll
            for (int c = 0; c < 4; c++) acc[a][b][c] = 0.f;

    // ---- B copy (always fp16 via cp.async): 4 x 16B chunks per thread ----
    auto cpB = [&](int s, int kt) {
        uint32_t st = smbase + s * STAGE_B + TILE_B;
        const int kof = kt * 64;
        #pragma unroll
        for (int i = 0; i < 4; i++) {
            int q = tid + i * 256;
            int r = q >> 3, ch = q & 7;
            cp16(st + r * ROWB + ch * 16, Bh + (size_t)(bn + r) * GK + kof + ch * 8);
        }
        asm volatile("cp.async.commit_group;" ::: "memory");
    };

    // ---- compute one k-tile from stage s ----
    auto compute = [&](int s) {
        uint32_t st = smbase + s * STAGE_B;
        #pragma unroll
        for (int ks = 0; ks < 4; ks++) {
            const int kof = ks * 16;
            uint32_t ah[4][4];
            #pragma unroll
            for (int mi = 0; mi < 4; mi++) {
                uint32_t addr = st + (wm + mi * 16 + (lane & 15)) * ROWB
                              + (kof + (lane >> 4) * 8) * 2;
                ldsm4(ah[mi], addr);
            }
            #pragma unroll
            for (int nip = 0; nip < 2; nip++) {
                uint32_t baddr = st + TILE_B
                               + (wn + nip * 16 + (lane & 7) + ((lane >> 4) << 3)) * ROWB
                               + (kof + ((lane >> 3) & 1) * 8) * 2;
                uint32_t bh[4];
                ldsm4(bh, baddr);
                #pragma unroll
                for (int mi = 0; mi < 4; mi++) {
                    mma16816(acc[mi][2 * nip],     ah[mi], bh[0], bh[1]);
                    mma16816(acc[mi][2 * nip + 1], ah[mi], bh[2], bh[3]);
                }
            }
        }
    };

    if (Afp32) {
        // ---- fp32 A: LDG next tile before compute, cvt+STS after ----
        float4 areg[8];
        auto ldgA = [&](int kt) {
            const int kof = kt * 64;
            #pragma unroll
            for (int i = 0; i < 8; i++) {
                int q = tid + i * 256;              // 0..2047
                int r = q >> 4, ch = q & 15;        // row 0..127, float4 col
                areg[i] = *reinterpret_cast<const float4*>(
                    Afp32 + (size_t)(bm + r) * GK + kof + ch * 4);
            }
        };
        auto stsA = [&](int s) {
            uint32_t st = smbase + s * STAGE_B;
            #pragma unroll
            for (int i = 0; i < 8; i++) {
                int q = tid + i * 256;
                int r = q >> 4, ch = q & 15;
                __half2 h01 = __floats2half2_rn(areg[i].x, areg[i].y);
                __half2 h23 = __floats2half2_rn(areg[i].z, areg[i].w);
                asm volatile("st.shared.v2.b32 [%0], {%1,%2};"
                             :: "r"(st + r * ROWB + ch * 8), "r"(h2u(h01)), "r"(h2u(h23)));
            }
        };

        ldgA(0); cpB(0, 0);
        stsA(0);
        for (int kt = 0; kt < NKT; kt++) {
            asm volatile("cp.async.wait_group 0;" ::: "memory");
            __syncthreads();
            if (kt + 1 < NKT) { ldgA(kt + 1); cpB((kt + 1) & 1, kt + 1); }
            compute(kt & 1);
            if (kt + 1 < NKT) stsA((kt + 1) & 1);
        }
    } else {
        // ---- fp16 A from g_Xh: cp.async both tiles ----
        auto cpA = [&](int s, int kt) {
            uint32_t st = smbase + s * STAGE_B;
            const int kof = kt * 64;
            #pragma unroll
            for (int i = 0; i < 4; i++) {
                int q = tid + i * 256;
                int r = q >> 3, ch = q & 7;
                cp16(st + r * ROWB + ch * 16, g_Xh + (size_t)(bm + r) * GK + kof + ch * 8);
            }
        };
        cpA(0, 0); cpB(0, 0);
        for (int kt = 0; kt < NKT; kt++) {
            asm volatile("cp.async.wait_group 0;" ::: "memory");
            __syncthreads();
            if (kt + 1 < NKT) { cpA((kt + 1) & 1, kt + 1); cpB((kt + 1) & 1, kt + 1); }
            compute(kt & 1);
        }
    }

    // epilogue: bias + store
    #pragma unroll
    for (int mi = 0; mi < 4; mi++) {
        int row = bm + wm + mi * 16 + gid;
        #pragma unroll
        for (int ni = 0; ni < 4; ni++) {
            int col = bn + wn + ni * 8 + tig * 2;
            float b0 = bias[col], b1 = bias[col + 1];
            float2 r01 = make_float2(acc[mi][ni][0] + b0, acc[mi][ni][1] + b1);
            float2 r23 = make_float2(acc[mi][ni][2] + b0, acc[mi][ni][3] + b1);
            *reinterpret_cast<float2*>(&C[(size_t)row * GN + col])       = r01;
            *reinterpret_cast<float2*>(&C[(size_t)(row + 8) * GN + col]) = r23;
        }
    }
}

// ---------------------------------------------------------------------------
// Per-position attention. Norms fused into the score loop (no separate
// phase/sync). Writes X fp16 into g_Xh ((B,H,S,D) layout).
// ---------------------------------------------------------------------------
__global__ __launch_bounds__(256) void attn_kernel(
    const float* __restrict__ SW, float* AT)
{
    const int p = blockIdx.x;
    const int b = p >> 12;
    const int s = p & 4095;
    const int tid = threadIdx.x;

    __shared__ __align__(16) float4 qs4[16][17];
    __shared__ __align__(16) float4 ks4[16][17];
    __shared__ __align__(16) float4 vs4[16][17];
    __shared__ float att[16][16];

    const size_t base = (size_t)p * 1024;
    const int r = tid >> 4, c = tid & 15;
    {
        size_t e = base + (size_t)tid * 4;
        qs4[r][c] = *reinterpret_cast<const float4*>(g_Q + e);
        ks4[r][c] = *reinterpret_cast<const float4*>(g_K + e);
        vs4[r][c] = *reinterpret_cast<const float4*>(g_V + e);
    }
    float w0, w1, w2;
    {
        float s0 = SW[0], s1 = SW[1], s2 = SW[2];
        float mx = fmaxf(s0, fmaxf(s1, s2));
        float e0 = expf(s0 - mx), e1 = expf(s1 - mx), e2 = expf(s2 - mx);
        float inv = 1.f / (e0 + e1 + e2);
        w0 = e0 * inv; w1 = e1 * inv; w2 = e2 * inv;
    }
    __syncthreads();

    // scores (+ fused norms) + softmax over j
    {
        int i = tid >> 4, j = tid & 15;
        float qk = 0.f, qq = 0.f, kk = 0.f;
        #pragma unroll
        for (int d = 0; d < 16; d++) {
            float4 a = qs4[i][d];
            float4 bv = ks4[j][d];
            qk += a.x * bv.x + a.y * bv.y + a.z * bv.z + a.w * bv.w;
            qq += a.x * a.x + a.y * a.y + a.z * a.z + a.w * a.w;
            kk += bv.x * bv.x + bv.y * bv.y + bv.z * bv.z + bv.w * bv.w;
        }
        float dots  = qk * 0.125f;
        float denom = fmaxf(sqrtf(qq) * sqrtf(kk), 1e-8f);
        float cosv  = qk / denom;
        float d2    = fmaxf(qq + kk - 2.f * qk, 0.f);
        float dist  = -sqrtf(d2);
        float sc = w0 * dots + w1 * cosv + w2 * dist;

        float mx = sc;
        #pragma unroll
        for (int o = 8; o; o >>= 1) mx = fmaxf(mx, __shfl_xor_sync(0xffffffffu, mx, o, 16));
        float e = expf(sc - mx);
        float sm = e;
        #pragma unroll
        for (int o = 8; o; o >>= 1) sm += __shfl_xor_sync(0xffffffffu, sm, o, 16);
        float a = e / sm;
        att[i][j] = a;
        if (AT) AT[(size_t)p * 256 + tid] = a;
    }
    __syncthreads();

    // out[i][d] = sum_j att[i][j] * v[j][d]; fp16 X (B,H,S,D)
    {
        int i = tid >> 4, cc = tid & 15;
        float4 o = make_float4(0.f, 0.f, 0.f, 0.f);
        #pragma unroll
        for (int j = 0; j < 16; j++) {
            float a = att[i][j];
            float4 v4 = vs4[j][cc];
            o.x += a * v4.x; o.y += a * v4.y; o.z += a * v4.z; o.w += a * v4.w;
        }
        size_t xidx = (size_t)b * 4194304 + (size_t)i * 262144 + (size_t)s * 64 + cc * 4;
        __half2 h01 = __floats2half2_rn(o.x, o.y);
        __half2 h23 = __floats2half2_rn(o.z, o.w);
        uint2 hp = make_uint2(h2u(h01), h2u(h23));
        *reinterpret_cast<uint2*>(&g_Xh[xidx]) = hp;
    }
}

// ---------------------------------------------------------------------------
// kernel_launch — 4th launch (profiled) is gemm_v.
// ---------------------------------------------------------------------------
extern "C" void kernel_launch(void* const* d_in, const int* in_sizes, int n_in,
                              void* d_out, int out_size) {
    (void)in_sizes; (void)n_in;
    const float* query = (const float*)d_in[0];
    const float* key   = (const float*)d_in[1];
    const float* value = (const float*)d_in[2];
    const float* Wq = (const float*)d_in[3];
    const float* bq = (const float*)d_in[4];
    const float* Wk = (const float*)d_in[5];
    const float* bk = (const float*)d_in[6];
    const float* Wv = (const float*)d_in[7];
    const float* bv = (const float*)d_in[8];
    const float* Wo = (const float*)d_in[9];
    const float* bo = (const float*)d_in[10];
    const float* sw = (const float*)d_in[11];
    float* out = (float*)d_out;

    static bool attr_set = false;
    if (!attr_set) {
        cudaFuncSetAttribute(gemm_tc_kernel,
                             cudaFuncAttributeMaxDynamicSharedMemorySize, GSMEM);
        attr_set = true;
    }

    dim3 ggrid(GN / 128, GM / 128);   // (8, 128)
    dim3 swgrid(GN / 32, GK / 32, 4); // (32, 32, 4)

    // 1: W^T splits
    split_wt4_kernel<<<swgrid, 256>>>(Wq, Wk, Wv, Wo);

    // 2,3,4: Q, K, V projections (fp32 A converted inline)
    gemm_tc_kernel<<<ggrid, 256, GSMEM>>>(query, 0, nullptr, 1, bq);
    gemm_tc_kernel<<<ggrid, 256, GSMEM>>>(key,   1, nullptr, 2, bk);
    gemm_tc_kernel<<<ggrid, 256, GSMEM>>>(value, 2, nullptr, 3, bv);

    // 5: attention (writes X fp16 into g_Xh)
    float* attn_dst = (out_size >= MAIN_OUT_ELEMS + ATT_ELEMS) ? (out + MAIN_OUT_ELEMS)
                                                               : nullptr;
    attn_kernel<<<NPOS, 256>>>(sw, attn_dst);

    // 6: output projection (fp16 A from g_Xh)
    gemm_tc_kernel<<<ggrid, 256, GSMEM>>>(nullptr, 3, out, 0, bo);
}

// round 14
// speedup vs baseline: 2.3810x; 1.0051x over previous
#include <cuda_runtime.h>
#include <cuda_fp16.h>
#include <stdint.h>

// Problem constants (B=4, S=4096, HID=1024, H=16, D=64)
#define GM 16384
#define GN 1024
#define GK 1024
#define NPOS 16384
#define ATT_ELEMS (NPOS * 256)
#define MAIN_OUT_ELEMS (GM * GN)
#define WSLOT ((size_t)GN * GK)

// Device-global scratch (no allocations allowed)
// Q/K/V projections stored fp16 (attention converts to fp32 in registers)
__device__ __align__(16) __half g_Qh[(size_t)GM * GN];
__device__ __align__(16) __half g_Kh[(size_t)GM * GN];
__device__ __align__(16) __half g_Vh[(size_t)GM * GN];
// X (attn output) fp16, (B,H,S,D) layout = A operand of output projection
__device__ __align__(16) __half g_Xh[(size_t)GM * GK];
// W^T fp16: slot 0..3 = Wq, Wk, Wv, Wo   ([n][k] layout)
__device__ __align__(16) __half g_Wth[4 * WSLOT];

// ---------------------------------------------------------------------------
// helpers
// ---------------------------------------------------------------------------
__device__ __forceinline__ void mma16816(float* c, const uint32_t* a, uint32_t b0, uint32_t b1) {
    asm volatile(
        "mma.sync.aligned.m16n8k16.row.col.f32.f16.f16.f32 "
        "{%0,%1,%2,%3}, {%4,%5,%6,%7}, {%8,%9}, {%0,%1,%2,%3};"
        : "+f"(c[0]), "+f"(c[1]), "+f"(c[2]), "+f"(c[3])
        : "r"(a[0]), "r"(a[1]), "r"(a[2]), "r"(a[3]), "r"(b0), "r"(b1));
}

__device__ __forceinline__ void ldsm4(uint32_t* r, uint32_t addr) {
    asm volatile("ldmatrix.sync.aligned.m8n8.x4.shared.b16 {%0,%1,%2,%3}, [%4];"
                 : "=r"(r[0]), "=r"(r[1]), "=r"(r[2]), "=r"(r[3]) : "r"(addr));
}

__device__ __forceinline__ void cp16(uint32_t dst, const void* src) {
    asm volatile("cp.async.cg.shared.global [%0], [%1], 16;" :: "r"(dst), "l"(src));
}

__device__ __forceinline__ uint32_t h2u(__half2 h) { return *reinterpret_cast<uint32_t*>(&h); }

// ---------------------------------------------------------------------------
// W split: fp32 [K,N] -> fp16 [N,K] (transpose). blockIdx.z selects W.
// ---------------------------------------------------------------------------
__global__ __launch_bounds__(256) void split_wt4_kernel(
    const float* __restrict__ w0, const float* __restrict__ w1,
    const float* __restrict__ w2, const float* __restrict__ w3)
{
    const int z = blockIdx.z;
    const float* W = (z == 0) ? w0 : (z == 1) ? w1 : (z == 2) ? w2 : w3;
    __half* Wh = g_Wth + (size_t)z * WSLOT;

    __shared__ float t[32][33];
    int n0 = blockIdx.x * 32, k0 = blockIdx.y * 32;
    int tx = threadIdx.x & 31, ty = threadIdx.x >> 5;
    #pragma unroll
    for (int j = 0; j < 4; j++)
        t[ty + 8 * j][tx] = W[(size_t)(k0 + ty + 8 * j) * GN + n0 + tx];
    __syncthreads();
    #pragma unroll
    for (int j = 0; j < 4; j++) {
        int r = ty + 8 * j;
        Wh[(size_t)(n0 + r) * GK + k0 + tx] = __float2half_rn(t[tx][r]);
    }
}

// ---------------------------------------------------------------------------
// GEMM: C = A @ W + bias. fp16 MMA operands, fp32 accumulate.
// A: fp32 (Afp32 != null, inline convert, LDG overlapped) or fp16 g_Xh.
// C: fp16 scratch (c_tag 1/2/3 -> g_Qh/g_Kh/g_Vh) or fp32 (Cout).
// CTA 128x128, BK=64, 256 threads = 8 warps (2x4), warp tile 64x32.
// ---------------------------------------------------------------------------
#define ROWB     144                 // bytes per smem row (128 data + 16 pad)
#define TILE_B   (128 * ROWB)        // 18432
#define STAGE_B  (2 * TILE_B)        // A + B tiles
#define GSMEM    (2 * STAGE_B)       // 73728
#define NKT      16                  // GK / 64

__device__ __forceinline__ __half* half_out_ptr(int tag) {
    switch (tag) { case 1: return g_Qh; case 2: return g_Kh;
                   case 3: return g_Vh; default: return nullptr; }
}

__global__ __launch_bounds__(256, 1) void gemm_tc_kernel(
    const float* __restrict__ Afp32, int w_slot,
    float* Cout, int c_tag, const float* __restrict__ bias)
{
    const __half* Bh = g_Wth + (size_t)w_slot * WSLOT;

    extern __shared__ __align__(16) char sm[];
    const uint32_t smbase = (uint32_t)__cvta_generic_to_shared(sm);

    const int tid  = threadIdx.x;
    const int warp = tid >> 5;
    const int lane = tid & 31;
    const int gid  = lane >> 2;
    const int tig  = lane & 3;
    const int wm = (warp >> 2) * 64;    // 0 or 64
    const int wn = (warp & 3) * 32;     // 0,32,64,96
    const int bm = blockIdx.y * 128;
    const int bn = blockIdx.x * 128;

    float acc[4][4][4];
    #pragma unroll
    for (int a = 0; a < 4; a++)
        #pragma unroll
        for (int b = 0; b < 4; b++)
            #pragma unroll
            for (int c = 0; c < 4; c++) acc[a][b][c] = 0.f;

    // ---- B copy (fp16 via cp.async) ----
    auto cpB = [&](int s, int kt) {
        uint32_t st = smbase + s * STAGE_B + TILE_B;
        const int kof = kt * 64;
        #pragma unroll
        for (int i = 0; i < 4; i++) {
            int q = tid + i * 256;
            int r = q >> 3, ch = q & 7;
            cp16(st + r * ROWB + ch * 16, Bh + (size_t)(bn + r) * GK + kof + ch * 8);
        }
        asm volatile("cp.async.commit_group;" ::: "memory");
    };

    // ---- compute one k-tile from stage s ----
    auto compute = [&](int s) {
        uint32_t st = smbase + s * STAGE_B;
        #pragma unroll
        for (int ks = 0; ks < 4; ks++) {
            const int kof = ks * 16;
            uint32_t ah[4][4];
            #pragma unroll
            for (int mi = 0; mi < 4; mi++) {
                uint32_t addr = st + (wm + mi * 16 + (lane & 15)) * ROWB
                              + (kof + (lane >> 4) * 8) * 2;
                ldsm4(ah[mi], addr);
            }
            #pragma unroll
            for (int nip = 0; nip < 2; nip++) {
                uint32_t baddr = st + TILE_B
                               + (wn + nip * 16 + (lane & 7) + ((lane >> 4) << 3)) * ROWB
                               + (kof + ((lane >> 3) & 1) * 8) * 2;
                uint32_t bh[4];
                ldsm4(bh, baddr);
                #pragma unroll
                for (int mi = 0; mi < 4; mi++) {
                    mma16816(acc[mi][2 * nip],     ah[mi], bh[0], bh[1]);
                    mma16816(acc[mi][2 * nip + 1], ah[mi], bh[2], bh[3]);
                }
            }
        }
    };

    if (Afp32) {
        // ---- fp32 A: LDG next tile before compute, cvt+STS after ----
        float4 areg[8];
        auto ldgA = [&](int kt) {
            const int kof = kt * 64;
            #pragma unroll
            for (int i = 0; i < 8; i++) {
                int q = tid + i * 256;
                int r = q >> 4, ch = q & 15;
                areg[i] = *reinterpret_cast<const float4*>(
                    Afp32 + (size_t)(bm + r) * GK + kof + ch * 4);
            }
        };
        auto stsA = [&](int s) {
            uint32_t st = smbase + s * STAGE_B;
            #pragma unroll
            for (int i = 0; i < 8; i++) {
                int q = tid + i * 256;
                int r = q >> 4, ch = q & 15;
                __half2 h01 = __floats2half2_rn(areg[i].x, areg[i].y);
                __half2 h23 = __floats2half2_rn(areg[i].z, areg[i].w);
                asm volatile("st.shared.v2.b32 [%0], {%1,%2};"
                             :: "r"(st + r * ROWB + ch * 8), "r"(h2u(h01)), "r"(h2u(h23)));
            }
        };

        ldgA(0); cpB(0, 0);
        stsA(0);
        for (int kt = 0; kt < NKT; kt++) {
            asm volatile("cp.async.wait_group 0;" ::: "memory");
            __syncthreads();
            if (kt + 1 < NKT) { ldgA(kt + 1); cpB((kt + 1) & 1, kt + 1); }
            compute(kt & 1);
            if (kt + 1 < NKT) stsA((kt + 1) & 1);
        }
    } else {
        // ---- fp16 A from g_Xh ----
        auto cpA = [&](int s, int kt) {
            uint32_t st = smbase + s * STAGE_B;
            const int kof = kt * 64;
            #pragma unroll
            for (int i = 0; i < 4; i++) {
                int q = tid + i * 256;
                int r = q >> 3, ch = q & 7;
                cp16(st + r * ROWB + ch * 16, g_Xh + (size_t)(bm + r) * GK + kof + ch * 8);
            }
        };
        cpA(0, 0); cpB(0, 0);
        for (int kt = 0; kt < NKT; kt++) {
            asm volatile("cp.async.wait_group 0;" ::: "memory");
            __syncthreads();
            if (kt + 1 < NKT) { cpA((kt + 1) & 1, kt + 1); cpB((kt + 1) & 1, kt + 1); }
            compute(kt & 1);
        }
    }

    // epilogue: bias + store (fp16 scratch or fp32 out)
    __half* Ch = half_out_ptr(c_tag);
    #pragma unroll
    for (int mi = 0; mi < 4; mi++) {
        int row = bm + wm + mi * 16 + gid;
        #pragma unroll
        for (int ni = 0; ni < 4; ni++) {
            int col = bn + wn + ni * 8 + tig * 2;
            float b0 = bias[col], b1 = bias[col + 1];
            float v0 = acc[mi][ni][0] + b0, v1 = acc[mi][ni][1] + b1;
            float v2 = acc[mi][ni][2] + b0, v3 = acc[mi][ni][3] + b1;
            if (Ch) {
                __half2 p01 = __floats2half2_rn(v0, v1);
                __half2 p23 = __floats2half2_rn(v2, v3);
                *reinterpret_cast<uint32_t*>(&Ch[(size_t)row * GN + col])       = h2u(p01);
                *reinterpret_cast<uint32_t*>(&Ch[(size_t)(row + 8) * GN + col]) = h2u(p23);
            } else {
                *reinterpret_cast<float2*>(&Cout[(size_t)row * GN + col])       = make_float2(v0, v1);
                *reinterpret_cast<float2*>(&Cout[(size_t)(row + 8) * GN + col]) = make_float2(v2, v3);
            }
        }
    }
}

// ---------------------------------------------------------------------------
// Per-position attention. Reads fp16 Q/K/V, converts to fp32; all math fp32.
// Norms fused into score loop. Writes X fp16 into g_Xh ((B,H,S,D) layout).
// ---------------------------------------------------------------------------
__global__ __launch_bounds__(256) void attn_kernel(
    const float* __restrict__ SW, float* AT)
{
    const int p = blockIdx.x;
    const int b = p >> 12;
    const int s = p & 4095;
    const int tid = threadIdx.x;

    __shared__ __align__(16) float4 qs4[16][17];
    __shared__ __align__(16) float4 ks4[16][17];
    __shared__ __align__(16) float4 vs4[16][17];
    __shared__ float att[16][16];

    const size_t base = (size_t)p * 1024;
    const int r = tid >> 4, c = tid & 15;
    {
        size_t e = base + (size_t)tid * 4;
        uint2 qr = *reinterpret_cast<const uint2*>(g_Qh + e);
        uint2 kr = *reinterpret_cast<const uint2*>(g_Kh + e);
        uint2 vr = *reinterpret_cast<const uint2*>(g_Vh + e);
        float2 q01 = __half22float2(*reinterpret_cast<__half2*>(&qr.x));
        float2 q23 = __half22float2(*reinterpret_cast<__half2*>(&qr.y));
        float2 k01 = __half22float2(*reinterpret_cast<__half2*>(&kr.x));
        float2 k23 = __half22float2(*reinterpret_cast<__half2*>(&kr.y));
        float2 v01 = __half22float2(*reinterpret_cast<__half2*>(&vr.x));
        float2 v23 = __half22float2(*reinterpret_cast<__half2*>(&vr.y));
        qs4[r][c] = make_float4(q01.x, q01.y, q23.x, q23.y);
        ks4[r][c] = make_float4(k01.x, k01.y, k23.x, k23.y);
        vs4[r][c] = make_float4(v01.x, v01.y, v23.x, v23.y);
    }
    float w0, w1, w2;
    {
        float s0 = SW[0], s1 = SW[1], s2 = SW[2];
        float mx = fmaxf(s0, fmaxf(s1, s2));
        float e0 = expf(s0 - mx), e1 = expf(s1 - mx), e2 = expf(s2 - mx);
        float inv = 1.f / (e0 + e1 + e2);
        w0 = e0 * inv; w1 = e1 * inv; w2 = e2 * inv;
    }
    __syncthreads();

    // scores (+ fused norms) + softmax over j
    {
        int i = tid >> 4, j = tid & 15;
        float qk = 0.f, qq = 0.f, kk = 0.f;
        #pragma unroll
        for (int d = 0; d < 16; d++) {
            float4 a = qs4[i][d];
            float4 bv = ks4[j][d];
            qk += a.x * bv.x + a.y * bv.y + a.z * bv.z + a.w * bv.w;
            qq += a.x * a.x + a.y * a.y + a.z * a.z + a.w * a.w;
            kk += bv.x * bv.x + bv.y * bv.y + bv.z * bv.z + bv.w * bv.w;
        }
        float dots  = qk * 0.125f;
        float denom = fmaxf(sqrtf(qq) * sqrtf(kk), 1e-8f);
        float cosv  = qk / denom;
        float d2    = fmaxf(qq + kk - 2.f * qk, 0.f);
        float dist  = -sqrtf(d2);
        float sc = w0 * dots + w1 * cosv + w2 * dist;

        float mx = sc;
        #pragma unroll
        for (int o = 8; o; o >>= 1) mx = fmaxf(mx, __shfl_xor_sync(0xffffffffu, mx, o, 16));
        float e = expf(sc - mx);
        float sm = e;
        #pragma unroll
        for (int o = 8; o; o >>= 1) sm += __shfl_xor_sync(0xffffffffu, sm, o, 16);
        float a = e / sm;
        att[i][j] = a;
        if (AT) AT[(size_t)p * 256 + tid] = a;
    }
    __syncthreads();

    // out[i][d] = sum_j att[i][j] * v[j][d]; fp16 X (B,H,S,D)
    {
        int i = tid >> 4, cc = tid & 15;
        float4 o = make_float4(0.f, 0.f, 0.f, 0.f);
        #pragma unroll
        for (int j = 0; j < 16; j++) {
            float a = att[i][j];
            float4 v4 = vs4[j][cc];
            o.x += a * v4.x; o.y += a * v4.y; o.z += a * v4.z; o.w += a * v4.w;
        }
        size_t xidx = (size_t)b * 4194304 + (size_t)i * 262144 + (size_t)s * 64 + cc * 4;
        __half2 h01 = __floats2half2_rn(o.x, o.y);
        __half2 h23 = __floats2half2_rn(o.z, o.w);
        uint2 hp = make_uint2(h2u(h01), h2u(h23));
        *reinterpret_cast<uint2*>(&g_Xh[xidx]) = hp;
    }
}

// ---------------------------------------------------------------------------
// kernel_launch — 4th launch (profiled) is gemm_v.
// ---------------------------------------------------------------------------
extern "C" void kernel_launch(void* const* d_in, const int* in_sizes, int n_in,
                              void* d_out, int out_size) {
    (void)in_sizes; (void)n_in;
    const float* query = (const float*)d_in[0];
    const float* key   = (const float*)d_in[1];
    const float* value = (const float*)d_in[2];
    const float* Wq = (const float*)d_in[3];
    const float* bq = (const float*)d_in[4];
    const float* Wk = (const float*)d_in[5];
    const float* bk = (const float*)d_in[6];
    const float* Wv = (const float*)d_in[7];
    const float* bv = (const float*)d_in[8];
    const float* Wo = (const float*)d_in[9];
    const float* bo = (const float*)d_in[10];
    const float* sw = (const float*)d_in[11];
    float* out = (float*)d_out;

    static bool attr_set = false;
    if (!attr_set) {
        cudaFuncSetAttribute(gemm_tc_kernel,
                             cudaFuncAttributeMaxDynamicSharedMemorySize, GSMEM);
        attr_set = true;
    }

    dim3 ggrid(GN / 128, GM / 128);   // (8, 128)
    dim3 swgrid(GN / 32, GK / 32, 4); // (32, 32, 4)

    // 1: W^T splits
    split_wt4_kernel<<<swgrid, 256>>>(Wq, Wk, Wv, Wo);

    // 2,3,4: Q, K, V projections (fp32 A inline-converted; fp16 C)
    gemm_tc_kernel<<<ggrid, 256, GSMEM>>>(query, 0, nullptr, 1, bq);
    gemm_tc_kernel<<<ggrid, 256, GSMEM>>>(key,   1, nullptr, 2, bk);
    gemm_tc_kernel<<<ggrid, 256, GSMEM>>>(value, 2, nullptr, 3, bv);

    // 5: attention (fp16 in, fp32 math, fp16 X out)
    float* attn_dst = (out_size >= MAIN_OUT_ELEMS + ATT_ELEMS) ? (out + MAIN_OUT_ELEMS)
                                                               : nullptr;
    attn_kernel<<<NPOS, 256>>>(sw, attn_dst);

    // 6: output projection (fp16 A from g_Xh; fp32 C = d_out)
    gemm_tc_kernel<<<ggrid, 256, GSMEM>>>(nullptr, 3, out, 0, bo);
}

// round 15
// speedup vs baseline: 2.5906x; 1.0880x over previous
#include <cuda_runtime.h>
#include <cuda_fp16.h>
#include <stdint.h>

// Problem constants (B=4, S=4096, HID=1024, H=16, D=64)
#define GM 16384
#define GN 1024
#define GK 1024
#define NPOS 16384
#define ATT_ELEMS (NPOS * 256)
#define MAIN_OUT_ELEMS (GM * GN)
#define WSLOT ((size_t)GN * GK)

// Device-global scratch (no allocations allowed)
__device__ __align__(16) __half g_Qh[(size_t)GM * GN];
__device__ __align__(16) __half g_Kh[(size_t)GM * GN];
__device__ __align__(16) __half g_Vh[(size_t)GM * GN];
__device__ __align__(16) __half g_Xh[(size_t)GM * GK];   // (B,H,S,D) fp16
__device__ __align__(16) __half g_Wth[4 * WSLOT];        // W^T fp16, slots 0..3

// ---------------------------------------------------------------------------
// helpers
// ---------------------------------------------------------------------------
__device__ __forceinline__ void mma16816(float* c, const uint32_t* a, uint32_t b0, uint32_t b1) {
    asm volatile(
        "mma.sync.aligned.m16n8k16.row.col.f32.f16.f16.f32 "
        "{%0,%1,%2,%3}, {%4,%5,%6,%7}, {%8,%9}, {%0,%1,%2,%3};"
        : "+f"(c[0]), "+f"(c[1]), "+f"(c[2]), "+f"(c[3])
        : "r"(a[0]), "r"(a[1]), "r"(a[2]), "r"(a[3]), "r"(b0), "r"(b1));
}

__device__ __forceinline__ void ldsm4(uint32_t* r, uint32_t addr) {
    asm volatile("ldmatrix.sync.aligned.m8n8.x4.shared.b16 {%0,%1,%2,%3}, [%4];"
                 : "=r"(r[0]), "=r"(r[1]), "=r"(r[2]), "=r"(r[3]) : "r"(addr));
}

__device__ __forceinline__ void cp16(uint32_t dst, const void* src) {
    asm volatile("cp.async.cg.shared.global [%0], [%1], 16;" :: "r"(dst), "l"(src));
}

__device__ __forceinline__ uint32_t h2u(__half2 h) { return *reinterpret_cast<uint32_t*>(&h); }

__device__ __forceinline__ float sumsq16(uint4 u) {
    const __half2* h = reinterpret_cast<const __half2*>(&u);
    float s = 0.f;
    #pragma unroll
    for (int i = 0; i < 4; i++) {
        float2 f = __half22float2(h[i]);
        s += f.x * f.x + f.y * f.y;
    }
    return s;
}

// ---------------------------------------------------------------------------
// W split: fp32 [K,N] -> fp16 [N,K] (transpose). blockIdx.z selects W.
// ---------------------------------------------------------------------------
__global__ __launch_bounds__(256) void split_wt4_kernel(
    const float* __restrict__ w0, const float* __restrict__ w1,
    const float* __restrict__ w2, const float* __restrict__ w3)
{
    const int z = blockIdx.z;
    const float* W = (z == 0) ? w0 : (z == 1) ? w1 : (z == 2) ? w2 : w3;
    __half* Wh = g_Wth + (size_t)z * WSLOT;

    __shared__ float t[32][33];
    int n0 = blockIdx.x * 32, k0 = blockIdx.y * 32;
    int tx = threadIdx.x & 31, ty = threadIdx.x >> 5;
    #pragma unroll
    for (int j = 0; j < 4; j++)
        t[ty + 8 * j][tx] = W[(size_t)(k0 + ty + 8 * j) * GN + n0 + tx];
    __syncthreads();
    #pragma unroll
    for (int j = 0; j < 4; j++) {
        int r = ty + 8 * j;
        Wh[(size_t)(n0 + r) * GK + k0 + tx] = __float2half_rn(t[tx][r]);
    }
}

// ---------------------------------------------------------------------------
// GEMM (unchanged from R14): C = A @ W + bias, fp16 MMA, fp32 accum.
// ---------------------------------------------------------------------------
#define ROWB     144
#define TILE_B   (128 * ROWB)
#define STAGE_B  (2 * TILE_B)
#define GSMEM    (2 * STAGE_B)       // 73728
#define NKT      16

__device__ __forceinline__ __half* half_out_ptr(int tag) {
    switch (tag) { case 1: return g_Qh; case 2: return g_Kh;
                   case 3: return g_Vh; default: return nullptr; }
}

__global__ __launch_bounds__(256, 1) void gemm_tc_kernel(
    const float* __restrict__ Afp32, int w_slot,
    float* Cout, int c_tag, const float* __restrict__ bias)
{
    const __half* Bh = g_Wth + (size_t)w_slot * WSLOT;

    extern __shared__ __align__(16) char sm[];
    const uint32_t smbase = (uint32_t)__cvta_generic_to_shared(sm);

    const int tid  = threadIdx.x;
    const int warp = tid >> 5;
    const int lane = tid & 31;
    const int gid  = lane >> 2;
    const int tig  = lane & 3;
    const int wm = (warp >> 2) * 64;
    const int wn = (warp & 3) * 32;
    const int bm = blockIdx.y * 128;
    const int bn = blockIdx.x * 128;

    float acc[4][4][4];
    #pragma unroll
    for (int a = 0; a < 4; a++)
        #pragma unroll
        for (int b = 0; b < 4; b++)
            #pragma unroll
            for (int c = 0; c < 4; c++) acc[a][b][c] = 0.f;

    auto cpB = [&](int s, int kt) {
        uint32_t st = smbase + s * STAGE_B + TILE_B;
        const int kof = kt * 64;
        #pragma unroll
        for (int i = 0; i < 4; i++) {
            int q = tid + i * 256;
            int r = q >> 3, ch = q & 7;
            cp16(st + r * ROWB + ch * 16, Bh + (size_t)(bn + r) * GK + kof + ch * 8);
        }
        asm volatile("cp.async.commit_group;" ::: "memory");
    };

    auto compute = [&](int s) {
        uint32_t st = smbase + s * STAGE_B;
        #pragma unroll
        for (int ks = 0; ks < 4; ks++) {
            const int kof = ks * 16;
            uint32_t ah[4][4];
            #pragma unroll
            for (int mi = 0; mi < 4; mi++) {
                uint32_t addr = st + (wm + mi * 16 + (lane & 15)) * ROWB
                              + (kof + (lane >> 4) * 8) * 2;
                ldsm4(ah[mi], addr);
            }
            #pragma unroll
            for (int nip = 0; nip < 2; nip++) {
                uint32_t baddr = st + TILE_B
                               + (wn + nip * 16 + (lane & 7) + ((lane >> 4) << 3)) * ROWB
                               + (kof + ((lane >> 3) & 1) * 8) * 2;
                uint32_t bh[4];
                ldsm4(bh, baddr);
                #pragma unroll
                for (int mi = 0; mi < 4; mi++) {
                    mma16816(acc[mi][2 * nip],     ah[mi], bh[0], bh[1]);
                    mma16816(acc[mi][2 * nip + 1], ah[mi], bh[2], bh[3]);
                }
            }
        }
    };

    if (Afp32) {
        float4 areg[8];
        auto ldgA = [&](int kt) {
            const int kof = kt * 64;
            #pragma unroll
            for (int i = 0; i < 8; i++) {
                int q = tid + i * 256;
                int r = q >> 4, ch = q & 15;
                areg[i] = *reinterpret_cast<const float4*>(
                    Afp32 + (size_t)(bm + r) * GK + kof + ch * 4);
            }
        };
        auto stsA = [&](int s) {
            uint32_t st = smbase + s * STAGE_B;
            #pragma unroll
            for (int i = 0; i < 8; i++) {
                int q = tid + i * 256;
                int r = q >> 4, ch = q & 15;
                __half2 h01 = __floats2half2_rn(areg[i].x, areg[i].y);
                __half2 h23 = __floats2half2_rn(areg[i].z, areg[i].w);
                asm volatile("st.shared.v2.b32 [%0], {%1,%2};"
                             :: "r"(st + r * ROWB + ch * 8), "r"(h2u(h01)), "r"(h2u(h23)));
            }
        };

        ldgA(0); cpB(0, 0);
        stsA(0);
        for (int kt = 0; kt < NKT; kt++) {
            asm volatile("cp.async.wait_group 0;" ::: "memory");
            __syncthreads();
            if (kt + 1 < NKT) { ldgA(kt + 1); cpB((kt + 1) & 1, kt + 1); }
            compute(kt & 1);
            if (kt + 1 < NKT) stsA((kt + 1) & 1);
        }
    } else {
        auto cpA = [&](int s, int kt) {
            uint32_t st = smbase + s * STAGE_B;
            const int kof = kt * 64;
            #pragma unroll
            for (int i = 0; i < 4; i++) {
                int q = tid + i * 256;
                int r = q >> 3, ch = q & 7;
                cp16(st + r * ROWB + ch * 16, g_Xh + (size_t)(bm + r) * GK + kof + ch * 8);
            }
        };
        cpA(0, 0); cpB(0, 0);
        for (int kt = 0; kt < NKT; kt++) {
            asm volatile("cp.async.wait_group 0;" ::: "memory");
            __syncthreads();
            if (kt + 1 < NKT) { cpA((kt + 1) & 1, kt + 1); cpB((kt + 1) & 1, kt + 1); }
            compute(kt & 1);
        }
    }

    __half* Ch = half_out_ptr(c_tag);
    #pragma unroll
    for (int mi = 0; mi < 4; mi++) {
        int row = bm + wm + mi * 16 + gid;
        #pragma unroll
        for (int ni = 0; ni < 4; ni++) {
            int col = bn + wn + ni * 8 + tig * 2;
            float b0 = bias[col], b1 = bias[col + 1];
            float v0 = acc[mi][ni][0] + b0, v1 = acc[mi][ni][1] + b1;
            float v2 = acc[mi][ni][2] + b0, v3 = acc[mi][ni][3] + b1;
            if (Ch) {
                __half2 p01 = __floats2half2_rn(v0, v1);
                __half2 p23 = __floats2half2_rn(v2, v3);
                *reinterpret_cast<uint32_t*>(&Ch[(size_t)row * GN + col])       = h2u(p01);
                *reinterpret_cast<uint32_t*>(&Ch[(size_t)(row + 8) * GN + col]) = h2u(p23);
            } else {
                *reinterpret_cast<float2*>(&Cout[(size_t)row * GN + col])       = make_float2(v0, v1);
                *reinterpret_cast<float2*>(&Cout[(size_t)(row + 8) * GN + col]) = make_float2(v2, v3);
            }
        }
    }
}

// ---------------------------------------------------------------------------
// Attention, warp-per-position, tensor cores.
// Scores: Q(16x64)@K^T via 8 MMAs (fp16 exact inputs, fp32 accum).
// Softmax in registers (shfl). AV: att(16x16)@V via 8 MMAs; the score
// accumulator layout IS the A-fragment layout (pack only).
// Per-warp smem: Qs 16x(64+8)h, Ks same, Vt 64x(16+8)h, qn/kn floats.
// ---------------------------------------------------------------------------
#define AW_QS   0
#define AW_KS   2304
#define AW_VT   4608
#define AW_QN   7680
#define AW_KN   7744
#define AW_SZ   7808
#define ASMEM   (8 * AW_SZ)   // 62464

__global__ __launch_bounds__(256) void attn_kernel(
    const float* __restrict__ SW, float* AT)
{
    extern __shared__ __align__(16) char dynsm[];
    const int warp = threadIdx.x >> 5;
    const int lane = threadIdx.x & 31;
    const int p = blockIdx.x * 8 + warp;
    const int b = p >> 12;
    const int s = p & 4095;

    char* wsm = dynsm + warp * AW_SZ;
    const uint32_t wsb = (uint32_t)__cvta_generic_to_shared(dynsm) + warp * AW_SZ;
    const size_t base = (size_t)p * 1024;

    float w0, w1, w2;
    {
        float s0 = SW[0], s1 = SW[1], s2 = SW[2];
        float mx = fmaxf(s0, fmaxf(s1, s2));
        float e0 = expf(s0 - mx), e1 = expf(s1 - mx), e2 = expf(s2 - mx);
        float inv = 1.f / (e0 + e1 + e2);
        w0 = e0 * inv; w1 = e1 * inv; w2 = e2 * inv;
    }

    // ---- load Q,K (row-major, 144B rows) with fused norms; V transposed ----
    {
        const int rw = lane >> 1, hp = lane & 1;
        const size_t go = base + (size_t)rw * 64 + hp * 32;

        uint4 q0 = *reinterpret_cast<const uint4*>(g_Qh + go);
        uint4 q1 = *reinterpret_cast<const uint4*>(g_Qh + go + 8);
        uint4 q2 = *reinterpret_cast<const uint4*>(g_Qh + go + 16);
        uint4 q3 = *reinterpret_cast<const uint4*>(g_Qh + go + 24);
        uint4* qdst = reinterpret_cast<uint4*>(wsm + AW_QS + rw * 144 + hp * 64);
        qdst[0] = q0; qdst[1] = q1; qdst[2] = q2; qdst[3] = q3;
        float qsum = sumsq16(q0) + sumsq16(q1) + sumsq16(q2) + sumsq16(q3);
        qsum += __shfl_xor_sync(0xffffffffu, qsum, 1);
        if (hp == 0) reinterpret_cast<float*>(wsm + AW_QN)[rw] = qsum;

        uint4 k0 = *reinterpret_cast<const uint4*>(g_Kh + go);
        uint4 k1 = *reinterpret_cast<const uint4*>(g_Kh + go + 8);
        uint4 k2 = *reinterpret_cast<const uint4*>(g_Kh + go + 16);
        uint4 k3 = *reinterpret_cast<const uint4*>(g_Kh + go + 24);
        uint4* kdst = reinterpret_cast<uint4*>(wsm + AW_KS + rw * 144 + hp * 64);
        kdst[0] = k0; kdst[1] = k1; kdst[2] = k2; kdst[3] = k3;
        float ksum = sumsq16(k0) + sumsq16(k1) + sumsq16(k2) + sumsq16(k3);
        ksum += __shfl_xor_sync(0xffffffffu, ksum, 1);
        if (hp == 0) reinterpret_cast<float*>(wsm + AW_KN)[rw] = ksum;

        // V transpose: Vt[d][j], row stride 24 halves (48B)
        __half* vt = reinterpret_cast<__half*>(wsm + AW_VT);
        uint4 v4[4];
        v4[0] = *reinterpret_cast<const uint4*>(g_Vh + go);
        v4[1] = *reinterpret_cast<const uint4*>(g_Vh + go + 8);
        v4[2] = *reinterpret_cast<const uint4*>(g_Vh + go + 16);
        v4[3] = *reinterpret_cast<const uint4*>(g_Vh + go + 24);
        #pragma unroll
        for (int q = 0; q < 4; q++) {
            const __half2* h = reinterpret_cast<const __half2*>(&v4[q]);
            #pragma unroll
            for (int m = 0; m < 4; m++) {
                int d = hp * 32 + q * 8 + m * 2;
                vt[d * 24 + rw]       = __low2half(h[m]);
                vt[(d + 1) * 24 + rw] = __high2half(h[m]);
            }
        }
    }
    __syncwarp();

    // ---- scores: 4 k-steps x 2 n-tiles of MMA ----
    float c0[4] = {0.f, 0.f, 0.f, 0.f};
    float c1[4] = {0.f, 0.f, 0.f, 0.f};
    #pragma unroll
    for (int kk = 0; kk < 4; kk++) {
        uint32_t a[4];
        ldsm4(a, wsb + AW_QS + (lane & 15) * 144 + (kk * 16 + (lane >> 4) * 8) * 2);
        uint32_t bb[4];
        ldsm4(bb, wsb + AW_KS + ((lane & 7) + ((lane >> 4) << 3)) * 144
                      + (kk * 16 + ((lane >> 3) & 1) * 8) * 2);
        mma16816(c0, a, bb[0], bb[1]);
        mma16816(c1, a, bb[2], bb[3]);
    }

    // ---- score transform + softmax (rows r and r+8 per lane) ----
    const int r = lane >> 2, tg = lane & 3;
    const float* qnp = reinterpret_cast<const float*>(wsm + AW_QN);
    const float* knp = reinterpret_cast<const float*>(wsm + AW_KN);
    float qq0 = qnp[r], qq8 = qnp[r + 8];
    float kn0 = knp[2 * tg], kn1 = knp[2 * tg + 1];
    float kn8 = knp[2 * tg + 8], kn9 = knp[2 * tg + 9];

    auto scf = [&](float qk, float qq, float kk) {
        float dots  = qk * 0.125f;
        float denom = fmaxf(sqrtf(qq) * sqrtf(kk), 1e-8f);
        float cosv  = qk / denom;
        float d2    = fmaxf(qq + kk - 2.f * qk, 0.f);
        return w0 * dots + w1 * cosv + w2 * (-sqrtf(d2));
    };

    float A = scf(c0[0], qq0, kn0), B = scf(c0[1], qq0, kn1);
    float C = scf(c0[2], qq8, kn0), D = scf(c0[3], qq8, kn1);
    float E = scf(c1[0], qq0, kn8), F = scf(c1[1], qq0, kn9);
    float G = scf(c1[2], qq8, kn8), H = scf(c1[3], qq8, kn9);

    float m0 = fmaxf(fmaxf(A, B), fmaxf(E, F));
    float m1 = fmaxf(fmaxf(C, D), fmaxf(G, H));
    m0 = fmaxf(m0, __shfl_xor_sync(0xffffffffu, m0, 1));
    m0 = fmaxf(m0, __shfl_xor_sync(0xffffffffu, m0, 2));
    m1 = fmaxf(m1, __shfl_xor_sync(0xffffffffu, m1, 1));
    m1 = fmaxf(m1, __shfl_xor_sync(0xffffffffu, m1, 2));

    float eA = expf(A - m0), eB = expf(B - m0), eE = expf(E - m0), eF = expf(F - m0);
    float eC = expf(C - m1), eD = expf(D - m1), eG = expf(G - m1), eH = expf(H - m1);
    float s0 = eA + eB + eE + eF;
    float s1 = eC + eD + eG + eH;
    s0 += __shfl_xor_sync(0xffffffffu, s0, 1);
    s0 += __shfl_xor_sync(0xffffffffu, s0, 2);
    s1 += __shfl_xor_sync(0xffffffffu, s1, 1);
    s1 += __shfl_xor_sync(0xffffffffu, s1, 2);
    float i0 = 1.f / s0, i1 = 1.f / s1;
    float aA = eA * i0, aB = eB * i0, aE = eE * i0, aF = eF * i0;
    float aC = eC * i1, aD = eD * i1, aG = eG * i1, aH = eH * i1;

    if (AT) {
        size_t pb = (size_t)p * 256;
        *reinterpret_cast<float2*>(&AT[pb + r * 16 + 2 * tg])           = make_float2(aA, aB);
        *reinterpret_cast<float2*>(&AT[pb + r * 16 + 8 + 2 * tg])       = make_float2(aE, aF);
        *reinterpret_cast<float2*>(&AT[pb + (r + 8) * 16 + 2 * tg])     = make_float2(aC, aD);
        *reinterpret_cast<float2*>(&AT[pb + (r + 8) * 16 + 8 + 2 * tg]) = make_float2(aG, aH);
    }

    // ---- AV: att accumulator layout == A fragment layout ----
    uint32_t af[4];
    af[0] = h2u(__floats2half2_rn(aA, aB));   // (r,   2tg..)
    af[1] = h2u(__floats2half2_rn(aC, aD));   // (r+8, 2tg..)
    af[2] = h2u(__floats2half2_rn(aE, aF));   // (r,   2tg+8..)
    af[3] = h2u(__floats2half2_rn(aG, aH));   // (r+8, 2tg+8..)

    float o[8][4];
    #pragma unroll
    for (int i = 0; i < 8; i++)
        #pragma unroll
        for (int j = 0; j < 4; j++) o[i][j] = 0.f;

    #pragma unroll
    for (int t2 = 0; t2 < 4; t2++) {
        uint32_t bb[4];
        ldsm4(bb, wsb + AW_VT + (t2 * 16 + (lane & 7) + ((lane >> 4) << 3)) * 48
                      + ((lane >> 3) & 1) * 16);
        mma16816(o[2 * t2],     af, bb[0], bb[1]);
        mma16816(o[2 * t2 + 1], af, bb[2], bb[3]);
    }

    // ---- store X fp16 (B,H,S,D): head = score row, d = AV col ----
    {
        size_t xb = (size_t)b * 4194304 + (size_t)s * 64;
        #pragma unroll
        for (int nt = 0; nt < 8; nt++) {
            int d0 = nt * 8 + 2 * tg;
            *reinterpret_cast<uint32_t*>(&g_Xh[xb + (size_t)r * 262144 + d0]) =
                h2u(__floats2half2_rn(o[nt][0], o[nt][1]));
            *reinterpret_cast<uint32_t*>(&g_Xh[xb + (size_t)(r + 8) * 262144 + d0]) =
                h2u(__floats2half2_rn(o[nt][2], o[nt][3]));
        }
    }
}

// ---------------------------------------------------------------------------
// kernel_launch
// ---------------------------------------------------------------------------
extern "C" void kernel_launch(void* const* d_in, const int* in_sizes, int n_in,
                              void* d_out, int out_size) {
    (void)in_sizes; (void)n_in;
    const float* query = (const float*)d_in[0];
    const float* key   = (const float*)d_in[1];
    const float* value = (const float*)d_in[2];
    const float* Wq = (const float*)d_in[3];
    const float* bq = (const float*)d_in[4];
    const float* Wk = (const float*)d_in[5];
    const float* bk = (const float*)d_in[6];
    const float* Wv = (const float*)d_in[7];
    const float* bv = (const float*)d_in[8];
    const float* Wo = (const float*)d_in[9];
    const float* bo = (const float*)d_in[10];
    const float* sw = (const float*)d_in[11];
    float* out = (float*)d_out;

    static bool attr_set = false;
    if (!attr_set) {
        cudaFuncSetAttribute(gemm_tc_kernel,
                             cudaFuncAttributeMaxDynamicSharedMemorySize, GSMEM);
        cudaFuncSetAttribute(attn_kernel,
                             cudaFuncAttributeMaxDynamicSharedMemorySize, ASMEM);
        attr_set = true;
    }

    dim3 ggrid(GN / 128, GM / 128);   // (8, 128)
    dim3 swgrid(GN / 32, GK / 32, 4); // (32, 32, 4)

    // 1: W^T splits
    split_wt4_kernel<<<swgrid, 256>>>(Wq, Wk, Wv, Wo);

    // 2,3,4: Q, K, V projections (fp32 A inline-converted; fp16 C)
    gemm_tc_kernel<<<ggrid, 256, GSMEM>>>(query, 0, nullptr, 1, bq);
    gemm_tc_kernel<<<ggrid, 256, GSMEM>>>(key,   1, nullptr, 2, bk);
    gemm_tc_kernel<<<ggrid, 256, GSMEM>>>(value, 2, nullptr, 3, bv);

    // 5: attention (warp per position; 8 positions per CTA)
    float* attn_dst = (out_size >= MAIN_OUT_ELEMS + ATT_ELEMS) ? (out + MAIN_OUT_ELEMS)
                                                               : nullptr;
    attn_kernel<<<NPOS / 8, 256, ASMEM>>>(sw, attn_dst);

    // 6: output projection (fp16 A from g_Xh; fp32 C = d_out)
    gemm_tc_kernel<<<ggrid, 256, GSMEM>>>(nullptr, 3, out, 0, bo);
}